// round 1
// baseline (speedup 1.0000x reference)
#include <cuda_runtime.h>

#define B_   2
#define G_   512
#define K_   32
#define D_   128
#define N_   16384
#define L_   50
#define LP_  52
#define S_   2
#define TPB  256

// ---------------- packed f32x2 helpers ----------------
__device__ __forceinline__ unsigned long long pack2(float x, float y) {
    unsigned long long r;
    asm("mov.b64 %0, {%1, %2};" : "=l"(r) : "f"(x), "f"(y));
    return r;
}
__device__ __forceinline__ void unpack2(unsigned long long v, float& x, float& y) {
    asm("mov.b64 {%0, %1}, %2;" : "=f"(x), "=f"(y) : "l"(v));
}
__device__ __forceinline__ void fma2(unsigned long long& d, unsigned long long a,
                                     unsigned long long b) {
    asm("fma.rn.f32x2 %0, %1, %2, %0;" : "+l"(d) : "l"(a), "l"(b));
}

// ---------------- shared memory layout ----------------
struct __align__(16) Smem {
    float F [K_][D_];        // gathered input feats
    float f1[K_][D_];        // stage-0 attention output
    float q [K_][D_];        // q of current stage; reused as stage-1 output
    float v [K_][D_];
    float kT[D_][33];        // transposed k, padded (stride 33 -> conflict-free)
    float hacc[K_][D_];      // trans accumulator
    float Tt[3][D_][LP_];    // tables transposed [t][d][l]
    float P [3][K_][LP_];    // projections k[i] . T_t[l]
    float attn[K_][K_];
    float cx[K_], cy[K_], cz[K_];
    float pooled[D_];
    int   gidx[K_];
};

// hacc += X @ trans_w[blk*128 : blk*128+128, :]   (blk 0 also adds trans_b)
__device__ __forceinline__ void trans_block(const float (*X)[D_], float (*H)[D_],
                                            const float* __restrict__ trans_w,
                                            const float* __restrict__ trans_b,
                                            int blk, int w, int lane)
{
    const int i0 = w * 4;
    const int c0 = lane * 4;
    unsigned long long acc[4][2];
    if (blk == 0) {
        float4 tb = *(const float4*)(trans_b + c0);
        unsigned long long t01 = pack2(tb.x, tb.y), t23 = pack2(tb.z, tb.w);
#pragma unroll
        for (int r = 0; r < 4; r++) { acc[r][0] = t01; acc[r][1] = t23; }
    } else {
#pragma unroll
        for (int r = 0; r < 4; r++) {
            ulonglong2 h = *(const ulonglong2*)&H[i0 + r][c0];
            acc[r][0] = h.x; acc[r][1] = h.y;
        }
    }
    const float* Wp = trans_w + (long long)blk * D_ * D_ + c0;
#pragma unroll 4
    for (int d = 0; d < D_; d++) {
        ulonglong2 wv = *(const ulonglong2*)(Wp + d * D_);
#pragma unroll
        for (int r = 0; r < 4; r++) {
            float a = X[i0 + r][d];
            unsigned long long a2 = pack2(a, a);
            fma2(acc[r][0], a2, wv.x);
            fma2(acc[r][1], a2, wv.y);
        }
    }
#pragma unroll
    for (int r = 0; r < 4; r++) {
        ulonglong2 o; o.x = acc[r][0]; o.y = acc[r][1];
        *(ulonglong2*)&H[i0 + r][c0] = o;
    }
}

__global__ void __launch_bounds__(TPB, 1)
voxel_encoder_kernel(const float* __restrict__ inputs,
                     const float* __restrict__ coordinates,
                     const float* __restrict__ qkv_w,
                     const float* __restrict__ qkv_b,
                     const float* __restrict__ table_x,
                     const float* __restrict__ table_y,
                     const float* __restrict__ table_z,
                     const float* __restrict__ trans_w,
                     const float* __restrict__ trans_b,
                     const float* __restrict__ ln_g,
                     const float* __restrict__ ln_b,
                     const int*   __restrict__ groups,
                     float* __restrict__ out,
                     float* __restrict__ ret)
{
    extern __shared__ __align__(16) char smem_raw[];
    Smem& s = *reinterpret_cast<Smem*>(smem_raw);

    const int tid  = threadIdx.x;
    const int w    = tid >> 5;
    const int lane = tid & 31;
    const int bg   = blockIdx.x;
    const int b    = bg / G_;
    const int g    = bg % G_;
    const int i0   = w * 4;
    const int c0   = lane * 4;

    // ---- gather point indices + coordinates ----
    if (tid < K_) {
        int p = groups[bg * K_ + tid];
        s.gidx[tid] = p;
        const float* c = coordinates + ((long long)b * N_ + p) * 3;
        s.cx[tid] = c[0]; s.cy[tid] = c[1]; s.cz[tid] = c[2];
    }
    __syncthreads();

    // ---- gather features [32][128] ----
#pragma unroll
    for (int rr = 0; rr < 4; rr++) {
        int e = tid + TPB * rr;
        int row = e >> 5, c4 = e & 31;
        float4 val = *(const float4*)(inputs + ((long long)b * N_ + s.gidx[row]) * D_ + c4 * 4);
        *(float4*)&s.F[row][c4 * 4] = val;
    }
    __syncthreads();

    // ---- trans block 0: hacc = trans_b + F @ Tw[0:128] ----
    trans_block(s.F, s.hacc, trans_w, trans_b, 0, w, lane);
    __syncthreads();

    // ================= attention stages =================
    for (int st = 0; st < S_; st++) {
        const float (*X)[D_]  = (st == 0) ? s.F  : s.f1;   // stage input
        float (*FO)[D_]       = (st == 0) ? s.f1 : s.q;    // stage output

        // ---- qkv GEMM: [32,128] @ [128,384] ----
        {
            const float* Wq = qkv_w + (long long)st * D_ * 3 * D_;
            unsigned long long acc[4][3][2];
            const float* bb = qkv_b + st * 3 * D_;
#pragma unroll
            for (int p = 0; p < 3; p++) {
                ulonglong2 bv = *(const ulonglong2*)(bb + p * D_ + c0);
#pragma unroll
                for (int r = 0; r < 4; r++) { acc[r][p][0] = bv.x; acc[r][p][1] = bv.y; }
            }
#pragma unroll 2
            for (int d = 0; d < D_; d++) {
                const float* wr = Wq + d * (3 * D_) + c0;
                ulonglong2 wq = *(const ulonglong2*)(wr);
                ulonglong2 wk = *(const ulonglong2*)(wr + D_);
                ulonglong2 wv = *(const ulonglong2*)(wr + 2 * D_);
#pragma unroll
                for (int r = 0; r < 4; r++) {
                    float a = X[i0 + r][d];
                    unsigned long long a2 = pack2(a, a);
                    fma2(acc[r][0][0], a2, wq.x); fma2(acc[r][0][1], a2, wq.y);
                    fma2(acc[r][1][0], a2, wk.x); fma2(acc[r][1][1], a2, wk.y);
                    fma2(acc[r][2][0], a2, wv.x); fma2(acc[r][2][1], a2, wv.y);
                }
            }
#pragma unroll
            for (int r = 0; r < 4; r++) {
                ulonglong2 oq; oq.x = acc[r][0][0]; oq.y = acc[r][0][1];
                *(ulonglong2*)&s.q[i0 + r][c0] = oq;
                ulonglong2 ov; ov.x = acc[r][2][0]; ov.y = acc[r][2][1];
                *(ulonglong2*)&s.v[i0 + r][c0] = ov;
                float k0, k1, k2, k3;
                unpack2(acc[r][1][0], k0, k1);
                unpack2(acc[r][1][1], k2, k3);
                s.kT[c0 + 0][i0 + r] = k0;
                s.kT[c0 + 1][i0 + r] = k1;
                s.kT[c0 + 2][i0 + r] = k2;
                s.kT[c0 + 3][i0 + r] = k3;
            }
        }
        __syncthreads();

        // ---- load + transpose tables into smem: Tt[t][d][l] ----
        {
            const long long toff = (long long)(st * 3 + 1) * L_ * D_;
            for (int e = tid; e < 3 * L_ * 32; e += TPB) {
                int t   = e / (L_ * 32);
                int rem = e - t * (L_ * 32);
                int l   = rem >> 5;
                int d4  = rem & 31;
                const float* tp = (t == 0 ? table_x : (t == 1 ? table_y : table_z)) + toff;
                float4 val = *(const float4*)(tp + l * D_ + d4 * 4);
                s.Tt[t][d4 * 4 + 0][l] = val.x;
                s.Tt[t][d4 * 4 + 1][l] = val.y;
                s.Tt[t][d4 * 4 + 2][l] = val.z;
                s.Tt[t][d4 * 4 + 3][l] = val.w;
            }
        }
        __syncthreads();

        // ---- projection GEMM: P[t][i][l] = sum_d kT[d][i] * Tt[t][d][l] ----
        if (lane < 25) {
            const int l0 = lane * 2;
            unsigned long long pacc[4][3];
#pragma unroll
            for (int r = 0; r < 4; r++)
#pragma unroll
                for (int t = 0; t < 3; t++) pacc[r][t] = 0ull;
#pragma unroll 2
            for (int d = 0; d < D_; d++) {
                unsigned long long t0 = *(const unsigned long long*)&s.Tt[0][d][l0];
                unsigned long long t1 = *(const unsigned long long*)&s.Tt[1][d][l0];
                unsigned long long t2 = *(const unsigned long long*)&s.Tt[2][d][l0];
#pragma unroll
                for (int r = 0; r < 4; r++) {
                    float kv = s.kT[d][i0 + r];
                    unsigned long long a2 = pack2(kv, kv);
                    fma2(pacc[r][0], a2, t0);
                    fma2(pacc[r][1], a2, t1);
                    fma2(pacc[r][2], a2, t2);
                }
            }
#pragma unroll
            for (int r = 0; r < 4; r++)
#pragma unroll
                for (int t = 0; t < 3; t++)
                    *(unsigned long long*)&s.P[t][i0 + r][l0] = pacc[r][t];
        }
        __syncthreads();

        // ---- scores[i][j] = q[i].k[j], warp w owns rows i0..i0+3, lane = j ----
        float sacc[4] = {0.f, 0.f, 0.f, 0.f};
#pragma unroll 4
        for (int d4 = 0; d4 < 32; d4++) {
            float kj0 = s.kT[d4 * 4 + 0][lane];
            float kj1 = s.kT[d4 * 4 + 1][lane];
            float kj2 = s.kT[d4 * 4 + 2][lane];
            float kj3 = s.kT[d4 * 4 + 3][lane];
#pragma unroll
            for (int r = 0; r < 4; r++) {
                float4 qv = *(const float4*)&s.q[i0 + r][d4 * 4];
                sacc[r] += qv.x * kj0 + qv.y * kj1 + qv.z * kj2 + qv.w * kj3;
            }
        }
        // ---- bias gather + softmax (per row, lane = j) ----
        {
            float cxj = s.cx[lane], cyj = s.cy[lane], czj = s.cz[lane];
#pragma unroll
            for (int r = 0; r < 4; r++) {
                int i = i0 + r;
                float dx = s.cx[i] - cxj;
                float dy = s.cy[i] - cyj;
                float dz = s.cz[i] - czj;
                int ix = min(max((int)floorf((dx + 0.25f) / 0.01f), 0), L_ - 1);
                int iy = min(max((int)floorf((dy + 0.25f) / 0.01f), 0), L_ - 1);
                int iz = min(max((int)floorf((dz + 0.25f) / 0.01f), 0), L_ - 1);
                float sc = (sacc[r] + s.P[0][i][ix] + s.P[1][i][iy] + s.P[2][i][iz])
                           * 0.08838834764831843f;   // 1/sqrt(128)
                float m = sc;
#pragma unroll
                for (int o = 16; o; o >>= 1) m = fmaxf(m, __shfl_xor_sync(0xffffffffu, m, o));
                float e = __expf(sc - m);
                float sum = e;
#pragma unroll
                for (int o = 16; o; o >>= 1) sum += __shfl_xor_sync(0xffffffffu, sum, o);
                s.attn[i][lane] = e * (1.0f / sum);
            }
        }
        __syncthreads();

        // ---- f = attn @ v : [32,32] @ [32,128] -> FO ----
        {
            unsigned long long facc[4][2];
#pragma unroll
            for (int r = 0; r < 4; r++) { facc[r][0] = 0ull; facc[r][1] = 0ull; }
#pragma unroll 4
            for (int j = 0; j < K_; j++) {
                ulonglong2 vj = *(const ulonglong2*)&s.v[j][c0];
#pragma unroll
                for (int r = 0; r < 4; r++) {
                    float a = s.attn[i0 + r][j];
                    unsigned long long a2 = pack2(a, a);
                    fma2(facc[r][0], a2, vj.x);
                    fma2(facc[r][1], a2, vj.y);
                }
            }
            __syncthreads();   // everyone done reading q/v before FO(=q at st=1) overwrite
#pragma unroll
            for (int r = 0; r < 4; r++) {
                ulonglong2 o; o.x = facc[r][0]; o.y = facc[r][1];
                *(ulonglong2*)&FO[i0 + r][c0] = o;
            }
        }
        __syncthreads();

        // ---- trans block (st+1): hacc += FO @ Tw[(st+1)*128 : ...] ----
        trans_block(FO, s.hacc, trans_w, trans_b, st + 1, w, lane);
        __syncthreads();
    }

    // ================= LayerNorm + ReLU (in place on hacc) =================
    {
        float4 g4 = *(const float4*)(ln_g + c0);
        float4 b4 = *(const float4*)(ln_b + c0);
#pragma unroll
        for (int r = 0; r < 4; r++) {
            int i = i0 + r;
            float4 h = *(const float4*)&s.hacc[i][c0];
            float s1 = h.x + h.y + h.z + h.w;
            float s2 = h.x * h.x + h.y * h.y + h.z * h.z + h.w * h.w;
#pragma unroll
            for (int o = 16; o; o >>= 1) {
                s1 += __shfl_xor_sync(0xffffffffu, s1, o);
                s2 += __shfl_xor_sync(0xffffffffu, s2, o);
            }
            float mu   = s1 * (1.0f / 128.0f);
            float var  = s2 * (1.0f / 128.0f) - mu * mu;
            float rstd = rsqrtf(var + 1e-5f);
            h.x = fmaxf((h.x - mu) * rstd * g4.x + b4.x, 0.0f);
            h.y = fmaxf((h.y - mu) * rstd * g4.y + b4.y, 0.0f);
            h.z = fmaxf((h.z - mu) * rstd * g4.z + b4.z, 0.0f);
            h.w = fmaxf((h.w - mu) * rstd * g4.w + b4.w, 0.0f);
            *(float4*)&s.hacc[i][c0] = h;
        }
    }
    __syncthreads();

    // ================= max-pool over points + outputs =================
    if (tid < D_) {
        float m = s.hacc[0][tid];
#pragma unroll
        for (int i = 1; i < K_; i++) m = fmaxf(m, s.hacc[i][tid]);
        s.pooled[tid] = m;
        int mm = g >> 6, nn = (g >> 3) & 7, tt = g & 7;
        int p = (tt << 6) + (nn << 3) + mm;          // transpose(0,3,2,1,4)
        out[((long long)b * G_ + p) * D_ + tid] = m;
    }
    __syncthreads();

    // scatter pooled feature back to every point of this voxel
#pragma unroll
    for (int rr = 0; rr < 4; rr++) {
        int e = tid + TPB * rr;
        int row = e >> 5, c4 = e & 31;
        float4 val = *(const float4*)&s.pooled[c4 * 4];
        *(float4*)(ret + ((long long)b * N_ + s.gidx[row]) * D_ + c4 * 4) = val;
    }
}

extern "C" void kernel_launch(void* const* d_in, const int* in_sizes, int n_in,
                              void* d_out, int out_size)
{
    const float* inputs      = (const float*)d_in[0];
    const float* coordinates = (const float*)d_in[1];
    const float* qkv_w       = (const float*)d_in[2];
    const float* qkv_b       = (const float*)d_in[3];
    const float* table_x     = (const float*)d_in[4];
    const float* table_y     = (const float*)d_in[5];
    const float* table_z     = (const float*)d_in[6];
    const float* trans_w     = (const float*)d_in[7];
    const float* trans_b     = (const float*)d_in[8];
    const float* ln_g        = (const float*)d_in[9];
    const float* ln_b        = (const float*)d_in[10];
    const int*   groups      = (const int*)d_in[11];
    // d_in[12] = effective_groups (unused by reference math)

    float* out = (float*)d_out;                         // [B, 512, 128]
    float* ret = out + (size_t)B_ * G_ * D_;            // [B, 16384, 128]

    cudaFuncSetAttribute(voxel_encoder_kernel,
                         cudaFuncAttributeMaxDynamicSharedMemorySize,
                         (int)sizeof(Smem));

    voxel_encoder_kernel<<<B_ * G_, TPB, sizeof(Smem)>>>(
        inputs, coordinates, qkv_w, qkv_b, table_x, table_y, table_z,
        trans_w, trans_b, ln_g, ln_b, groups, out, ret);
}

// round 2
// speedup vs baseline: 1.7321x; 1.7321x over previous
#include <cuda_runtime.h>

#define B_   2
#define G_   512
#define K_   32
#define D_   128
#define N_   16384
#define L_   50
#define LP_  52
#define S_   2
#define TPB  256
#define KPAD 132

typedef unsigned long long ull;

// ---------------- packed f32x2 helpers ----------------
__device__ __forceinline__ ull pack2(float x, float y) {
    ull r;
    asm("mov.b64 %0, {%1, %2};" : "=l"(r) : "f"(x), "f"(y));
    return r;
}
__device__ __forceinline__ void fma2(ull& d, ull a, ull b) {
    asm("fma.rn.f32x2 %0, %1, %2, %0;" : "+l"(d) : "l"(a), "l"(b));
}

// ---------------- shared memory layout (~112 KB -> 2 CTAs/SM) ----------------
struct __align__(16) Smem {
    float F [K_][D_];          // stage input X (both stages); stage-0 output f1
    float qP[3 * K_ * LP_];    // union: q[32][128] -> P[3][32][52] -> f2[32][128]
    float v [K_][D_];
    float k [K_][KPAD];        // row-major k, 132-pad (conflict-free LDS.128)
    float hacc[K_][D_];        // trans accumulator
    float Tt[3][32][LP_];      // table chunk, transposed [t][d_local][l]
    float attn[K_][K_];
    float cx[K_], cy[K_], cz[K_];
    float pooled[D_];
    int   gidx[K_];
};

// hacc += X @ trans_w[blk*128 .. +128, :]; blk 0 seeds with trans_b.
// Warp split: 4 row-groups x 2 col-groups (8 rows, 64 cols per warp).
__device__ __forceinline__ void trans_block(const float* __restrict__ X,   // row stride 128
                                            float (*H)[D_],
                                            const float* __restrict__ trans_w,
                                            const float* __restrict__ trans_b,
                                            int blk, int w, int lane)
{
    const int r0 = (w >> 1) * 8;
    const int cB = (w & 1) * 64 + 2 * lane;
    ull acc[8];
    if (blk == 0) {
        ull b = *(const ull*)(trans_b + cB);
#pragma unroll
        for (int r = 0; r < 8; r++) acc[r] = b;
    } else {
#pragma unroll
        for (int r = 0; r < 8; r++) acc[r] = *(const ull*)&H[r0 + r][cB];
    }
    const float* Wp = trans_w + blk * D_ * D_ + cB;
    for (int d4 = 0; d4 < 32; d4++) {
        float xv[8][4];
#pragma unroll
        for (int r = 0; r < 8; r++)
            *(float4*)&xv[r][0] = *(const float4*)(X + (r0 + r) * D_ + d4 * 4);
#pragma unroll
        for (int s2 = 0; s2 < 4; s2++) {
            ull wv = *(const ull*)(Wp + (d4 * 4 + s2) * D_);
#pragma unroll
            for (int r = 0; r < 8; r++)
                fma2(acc[r], pack2(xv[r][s2], xv[r][s2]), wv);
        }
    }
#pragma unroll
    for (int r = 0; r < 8; r++) *(ull*)&H[r0 + r][cB] = acc[r];
}

__global__ void __launch_bounds__(TPB, 2)
voxel_encoder_kernel(const float* __restrict__ inputs,
                     const float* __restrict__ coordinates,
                     const float* __restrict__ qkv_w,
                     const float* __restrict__ qkv_b,
                     const float* __restrict__ table_x,
                     const float* __restrict__ table_y,
                     const float* __restrict__ table_z,
                     const float* __restrict__ trans_w,
                     const float* __restrict__ trans_b,
                     const float* __restrict__ ln_g,
                     const float* __restrict__ ln_b,
                     const int*   __restrict__ groups,
                     float* __restrict__ out,
                     float* __restrict__ ret)
{
    extern __shared__ __align__(16) char smem_raw[];
    Smem& s = *reinterpret_cast<Smem*>(smem_raw);

    const int tid  = threadIdx.x;
    const int w    = tid >> 5;
    const int lane = tid & 31;
    const int bg   = blockIdx.x;
    const int b    = bg / G_;
    const int g    = bg % G_;
    const int i0   = w * 4;          // attention row mapping (4 rows/warp)
    const int c0   = lane * 4;

    // ---- gather point indices + coordinates ----
    if (tid < K_) {
        int p = groups[bg * K_ + tid];
        s.gidx[tid] = p;
        const float* c = coordinates + ((long long)b * N_ + p) * 3;
        s.cx[tid] = c[0]; s.cy[tid] = c[1]; s.cz[tid] = c[2];
    }
    __syncthreads();

    // ---- gather features [32][128] ----
#pragma unroll
    for (int rr = 0; rr < 4; rr++) {
        int e = tid + TPB * rr;
        int row = e >> 5, c4 = e & 31;
        float4 val = *(const float4*)(inputs + ((long long)b * N_ + s.gidx[row]) * D_ + c4 * 4);
        *(float4*)&s.F[row][c4 * 4] = val;
    }
    __syncthreads();

    // ---- trans block 0 (reads F; hacc disjoint; warp-local accumulation) ----
    trans_block(&s.F[0][0], s.hacc, trans_w, trans_b, 0, w, lane);

    // ================= attention stages =================
    for (int st = 0; st < S_; st++) {
        const float* Xb  = &s.F[0][0];                    // stage input
        float*       FOb = (st == 0) ? &s.F[0][0] : s.qP; // stage output

        // ---- qkv GEMM: [32,128] @ [128,384]; 4 row-groups x 2 col-groups ----
        {
            const int r0 = (w >> 1) * 8;
            const int cw = w & 1;
            const int cA = cw * 192 + 2 * lane;           // global col of pair 0
            const float* Wq = qkv_w + (long long)st * D_ * 3 * D_;
            const float* bb = qkv_b + st * 3 * D_;

            ull acc[8][3];
            {
                ull b0 = *(const ull*)(bb + cA);
                ull b1 = *(const ull*)(bb + cA + 64);
                ull b2 = *(const ull*)(bb + cA + 128);
#pragma unroll
                for (int r = 0; r < 8; r++) { acc[r][0] = b0; acc[r][1] = b1; acc[r][2] = b2; }
            }
            for (int d4 = 0; d4 < 32; d4++) {
                float xv[8][4];
#pragma unroll
                for (int r = 0; r < 8; r++)
                    *(float4*)&xv[r][0] = *(const float4*)(Xb + (r0 + r) * D_ + d4 * 4);
#pragma unroll
                for (int s2 = 0; s2 < 4; s2++) {
                    const float* wr = Wq + (d4 * 4 + s2) * (3 * D_) + cA;
                    ull w0 = *(const ull*)(wr);
                    ull w1 = *(const ull*)(wr + 64);
                    ull w2 = *(const ull*)(wr + 128);
#pragma unroll
                    for (int r = 0; r < 8; r++) {
                        ull a2 = pack2(xv[r][s2], xv[r][s2]);
                        fma2(acc[r][0], a2, w0);
                        fma2(acc[r][1], a2, w1);
                        fma2(acc[r][2], a2, w2);
                    }
                }
            }
            // writeback: cw0 -> q(0..63), q(64..127), k(0..63)
            //            cw1 -> k(64..127), v(0..63), v(64..127)
            if (cw == 0) {
#pragma unroll
                for (int r = 0; r < 8; r++) {
                    int row = r0 + r;
                    *(ull*)&s.qP[row * D_ + 2 * lane]       = acc[r][0];
                    *(ull*)&s.qP[row * D_ + 64 + 2 * lane]  = acc[r][1];
                    *(ull*)&s.k [row][2 * lane]             = acc[r][2];
                }
            } else {
#pragma unroll
                for (int r = 0; r < 8; r++) {
                    int row = r0 + r;
                    *(ull*)&s.k[row][64 + 2 * lane] = acc[r][0];
                    *(ull*)&s.v[row][2 * lane]      = acc[r][1];
                    *(ull*)&s.v[row][64 + 2 * lane] = acc[r][2];
                }
            }
        }
        __syncthreads();

        // ---- raw scores[i][j] = q[i].k[j]; warp w rows i0..i0+3, lane = j ----
        float sacc[4] = {0.f, 0.f, 0.f, 0.f};
#pragma unroll 4
        for (int d4 = 0; d4 < 32; d4++) {
            float4 kj = *(const float4*)&s.k[lane][d4 * 4];
#pragma unroll
            for (int r = 0; r < 4; r++) {
                float4 qv = *(const float4*)&s.qP[(i0 + r) * D_ + d4 * 4];
                sacc[r] += qv.x * kj.x + qv.y * kj.y + qv.z * kj.z + qv.w * kj.w;
            }
        }

        // ---- projection GEMM: P[t][i][l] = sum_d k[i][d]*T_t[l][d], chunked d ----
        {
            const long long toff = (long long)(st * 3 + 1) * L_ * D_;
            const int l0 = lane * 2;
            ull pacc[4][3];
#pragma unroll
            for (int r = 0; r < 4; r++)
#pragma unroll
                for (int t = 0; t < 3; t++) pacc[r][t] = 0ull;

            for (int c = 0; c < 4; c++) {          // 4 chunks of 32 d
                const int d0 = c * 32;
                __syncthreads();                   // prev chunk consumed
                for (int e = tid; e < 1200; e += TPB) {
                    int t   = e / 400;
                    int rem = e - t * 400;
                    int l   = rem >> 3;
                    int d8  = rem & 7;
                    const float* tp = (t == 0 ? table_x : (t == 1 ? table_y : table_z)) + toff;
                    float4 val = *(const float4*)(tp + l * D_ + d0 + d8 * 4);
                    s.Tt[t][d8 * 4 + 0][l] = val.x;
                    s.Tt[t][d8 * 4 + 1][l] = val.y;
                    s.Tt[t][d8 * 4 + 2][l] = val.z;
                    s.Tt[t][d8 * 4 + 3][l] = val.w;
                }
                __syncthreads();
                if (lane < 25) {
                    for (int dd4 = 0; dd4 < 8; dd4++) {
                        float kv[4][4];
#pragma unroll
                        for (int r = 0; r < 4; r++)
                            *(float4*)&kv[r][0] = *(const float4*)&s.k[i0 + r][d0 + dd4 * 4];
#pragma unroll
                        for (int s2 = 0; s2 < 4; s2++) {
                            int dd = dd4 * 4 + s2;
                            ull t0 = *(const ull*)&s.Tt[0][dd][l0];
                            ull t1 = *(const ull*)&s.Tt[1][dd][l0];
                            ull t2 = *(const ull*)&s.Tt[2][dd][l0];
#pragma unroll
                            for (int r = 0; r < 4; r++) {
                                ull a2 = pack2(kv[r][s2], kv[r][s2]);
                                fma2(pacc[r][0], a2, t0);
                                fma2(pacc[r][1], a2, t1);
                                fma2(pacc[r][2], a2, t2);
                            }
                        }
                    }
                }
            }
            if (lane < 25) {
#pragma unroll
                for (int r = 0; r < 4; r++)
#pragma unroll
                    for (int t = 0; t < 3; t++)
                        *(ull*)&s.qP[((t * K_) + i0 + r) * LP_ + l0] = pacc[r][t];
            }
            __syncwarp();   // P written by lanes<25, read by all lanes of this warp
        }

        // ---- bias gather + softmax (rows warp-local; P rows warp-local) ----
        {
            float cxj = s.cx[lane], cyj = s.cy[lane], czj = s.cz[lane];
#pragma unroll
            for (int r = 0; r < 4; r++) {
                int i = i0 + r;
                float dx = s.cx[i] - cxj;
                float dy = s.cy[i] - cyj;
                float dz = s.cz[i] - czj;
                int ix = min(max((int)floorf((dx + 0.25f) / 0.01f), 0), L_ - 1);
                int iy = min(max((int)floorf((dy + 0.25f) / 0.01f), 0), L_ - 1);
                int iz = min(max((int)floorf((dz + 0.25f) / 0.01f), 0), L_ - 1);
                float sc = (sacc[r]
                            + s.qP[(0 * K_ + i) * LP_ + ix]
                            + s.qP[(1 * K_ + i) * LP_ + iy]
                            + s.qP[(2 * K_ + i) * LP_ + iz])
                           * 0.08838834764831843f;    // 1/sqrt(128)
                float m = sc;
#pragma unroll
                for (int o = 16; o; o >>= 1) m = fmaxf(m, __shfl_xor_sync(0xffffffffu, m, o));
                float e = __expf(sc - m);
                float sum = e;
#pragma unroll
                for (int o = 16; o; o >>= 1) sum += __shfl_xor_sync(0xffffffffu, sum, o);
                s.attn[i][lane] = e * (1.0f / sum);
            }
        }
        __syncthreads();   // all warps done with q/P region before FO overwrite

        // ---- f = attn @ v : [32,32] @ [32,128] -> FO ----
        {
            ull facc[4][2];
#pragma unroll
            for (int r = 0; r < 4; r++) { facc[r][0] = 0ull; facc[r][1] = 0ull; }
#pragma unroll 4
            for (int j = 0; j < K_; j++) {
                ulonglong2 vj = *(const ulonglong2*)&s.v[j][c0];
#pragma unroll
                for (int r = 0; r < 4; r++) {
                    float a = s.attn[i0 + r][j];
                    ull a2 = pack2(a, a);
                    fma2(facc[r][0], a2, vj.x);
                    fma2(facc[r][1], a2, vj.y);
                }
            }
#pragma unroll
            for (int r = 0; r < 4; r++) {
                ulonglong2 o; o.x = facc[r][0]; o.y = facc[r][1];
                *(ulonglong2*)(FOb + (i0 + r) * D_ + c0) = o;
            }
        }
        __syncthreads();

        // ---- trans block (st+1): hacc += FO @ Tw[(st+1)*128 ..] ----
        trans_block(FOb, s.hacc, trans_w, trans_b, st + 1, w, lane);
        __syncthreads();
    }

    // ================= LayerNorm + ReLU (in place on hacc) =================
    {
        float4 g4 = *(const float4*)(ln_g + c0);
        float4 b4 = *(const float4*)(ln_b + c0);
#pragma unroll
        for (int r = 0; r < 4; r++) {
            int i = i0 + r;
            float4 h = *(const float4*)&s.hacc[i][c0];
            float s1 = h.x + h.y + h.z + h.w;
            float s2 = h.x * h.x + h.y * h.y + h.z * h.z + h.w * h.w;
#pragma unroll
            for (int o = 16; o; o >>= 1) {
                s1 += __shfl_xor_sync(0xffffffffu, s1, o);
                s2 += __shfl_xor_sync(0xffffffffu, s2, o);
            }
            float mu   = s1 * (1.0f / 128.0f);
            float var  = s2 * (1.0f / 128.0f) - mu * mu;
            float rstd = rsqrtf(var + 1e-5f);
            h.x = fmaxf((h.x - mu) * rstd * g4.x + b4.x, 0.0f);
            h.y = fmaxf((h.y - mu) * rstd * g4.y + b4.y, 0.0f);
            h.z = fmaxf((h.z - mu) * rstd * g4.z + b4.z, 0.0f);
            h.w = fmaxf((h.w - mu) * rstd * g4.w + b4.w, 0.0f);
            *(float4*)&s.hacc[i][c0] = h;
        }
    }
    __syncthreads();

    // ================= max-pool over points + outputs =================
    if (tid < D_) {
        float m = s.hacc[0][tid];
#pragma unroll
        for (int i = 1; i < K_; i++) m = fmaxf(m, s.hacc[i][tid]);
        s.pooled[tid] = m;
        int mm = g >> 6, nn = (g >> 3) & 7, tt = g & 7;
        int p = (tt << 6) + (nn << 3) + mm;          // transpose(0,3,2,1,4)
        out[((long long)b * G_ + p) * D_ + tid] = m;
    }
    __syncthreads();

    // scatter pooled feature back to every point of this voxel
#pragma unroll
    for (int rr = 0; rr < 4; rr++) {
        int e = tid + TPB * rr;
        int row = e >> 5, c4 = e & 31;
        float4 val = *(const float4*)&s.pooled[c4 * 4];
        *(float4*)(ret + ((long long)b * N_ + s.gidx[row]) * D_ + c4 * 4) = val;
    }
}

extern "C" void kernel_launch(void* const* d_in, const int* in_sizes, int n_in,
                              void* d_out, int out_size)
{
    const float* inputs      = (const float*)d_in[0];
    const float* coordinates = (const float*)d_in[1];
    const float* qkv_w       = (const float*)d_in[2];
    const float* qkv_b       = (const float*)d_in[3];
    const float* table_x     = (const float*)d_in[4];
    const float* table_y     = (const float*)d_in[5];
    const float* table_z     = (const float*)d_in[6];
    const float* trans_w     = (const float*)d_in[7];
    const float* trans_b     = (const float*)d_in[8];
    const float* ln_g        = (const float*)d_in[9];
    const float* ln_b        = (const float*)d_in[10];
    const int*   groups      = (const int*)d_in[11];
    // d_in[12] = effective_groups (unused by reference math)

    float* out = (float*)d_out;                         // [B, 512, 128]
    float* ret = out + (size_t)B_ * G_ * D_;            // [B, 16384, 128]

    cudaFuncSetAttribute(voxel_encoder_kernel,
                         cudaFuncAttributeMaxDynamicSharedMemorySize,
                         (int)sizeof(Smem));

    voxel_encoder_kernel<<<B_ * G_, TPB, sizeof(Smem)>>>(
        inputs, coordinates, qkv_w, qkv_b, table_x, table_y, table_z,
        trans_w, trans_b, ln_g, ln_b, groups, out, ret);
}

// round 3
// speedup vs baseline: 2.2558x; 1.3023x over previous
#include <cuda_runtime.h>

#define B_   2
#define G_   512
#define K_   32
#define D_   128
#define N_   16384
#define L_   50
#define S_   2
#define TPB  256
#define PX   132     // row stride (floats) for 32x128 tiles: conflict-free frag loads
#define PT   36      // pad for Tt rows / attn / scores / vT
#define PW   392     // qkv W slab row pad
#define PU   136     // trans W slab row pad

typedef unsigned long long ull;
typedef unsigned int u32;

__device__ __forceinline__ ull pack2(float x, float y) {
    ull r; asm("mov.b64 %0, {%1, %2};" : "=l"(r) : "f"(x), "f"(y)); return r;
}
__device__ __forceinline__ u32 tf(float x) {
    u32 r; asm("cvt.rna.tf32.f32 %0, %1;" : "=r"(r) : "f"(x)); return r;
}
__device__ __forceinline__ void mma8(float* c, const u32* a, const u32* b) {
    asm("mma.sync.aligned.m16n8k8.row.col.f32.tf32.tf32.f32 "
        "{%0,%1,%2,%3},{%4,%5,%6,%7},{%8,%9},{%0,%1,%2,%3};"
        : "+f"(c[0]), "+f"(c[1]), "+f"(c[2]), "+f"(c[3])
        : "r"(a[0]), "r"(a[1]), "r"(a[2]), "r"(a[3]), "r"(b[0]), "r"(b[1]));
}

// A fragment: A[mr + row][kc + col], row-major smem, given stride
__device__ __forceinline__ void ldA(u32* a, const float* S, int stride, int mr, int kc, int lane) {
    const float* p = S + (mr + (lane >> 2)) * stride + kc + (lane & 3);
    a[0] = tf(p[0]); a[1] = tf(p[8 * stride]); a[2] = tf(p[4]); a[3] = tf(p[8 * stride + 4]);
}
// B fragment from k-major storage: value B[k][n] at S[k*stride + n]
__device__ __forceinline__ void ldBk(u32* b, const float* S, int stride, int kc, int nc, int lane) {
    const float* p = S + (kc + (lane & 3)) * stride + nc + (lane >> 2);
    b[0] = tf(p[0]); b[1] = tf(p[4 * stride]);
}
// B fragment from n-major storage: value B[k][n] at S[n*stride + k]
__device__ __forceinline__ void ldBn(u32* b, const float* S, int stride, int nc, int kc, int lane) {
    const float* p = S + (nc + (lane >> 2)) * stride + kc + (lane & 3);
    b[0] = tf(p[0]); b[1] = tf(p[4]);
}

// ---------------- shared memory (~105 KB -> 2 CTAs/SM) ----------------
struct __align__(16) Smem {
    float U1[3 * K_ * 56];   // X [32][132] (4224 f)  UNION  P [3][32][56] (5376 f)
    float q [K_ * PX];
    float k [K_ * PX];
    float vT[D_ * PT];       // v transposed [128][36]
    float sa[K_ * PT];       // scores -> attn [32][36]
    float U2[16 * PW];       // qkv slab [16][392] U Tt [3][56][36] U trans slab [32][136]
    float cx[K_], cy[K_], cz[K_];
    float pooled[D_];
    int   gidx[K_];
};

// hacc(ht) += X @ trans_w_block; warp w owns cols [16w,16w+16), all 32 rows
__device__ __forceinline__ void trans_mma(const float* __restrict__ X, float* __restrict__ slab,
                                          const float* __restrict__ W, float ht[2][2][4],
                                          int w, int lane)
{
    const int nT = w * 16;
    for (int ch = 0; ch < 4; ch++) {               // 4 chunks of 32 k-rows
        __syncthreads();
        for (int t = threadIdx.x; t < 32 * 32; t += TPB) {
            int kk = t >> 5, n4 = t & 31;
            *(float4*)&slab[kk * PU + n4 * 4] =
                *(const float4*)(W + (ch * 32 + kk) * D_ + n4 * 4);
        }
        __syncthreads();
#pragma unroll
        for (int k8 = 0; k8 < 4; k8++) {
            int kc = k8 * 8;
            u32 a0[4], a1[4];
            ldA(a0, X, PX, 0,  kc, lane);   // wait—A cols are within chunk? no: X col = ch*32+kc
            ldA(a1, X, PX, 16, kc, lane);
            // fix: reload with global column (see below) -- replaced:
            (void)a0; (void)a1;
            u32 A0[4], A1[4];
            ldA(A0, X, PX, 0,  ch * 32 + kc, lane);
            ldA(A1, X, PX, 16, ch * 32 + kc, lane);
#pragma unroll
            for (int j = 0; j < 2; j++) {
                u32 b[2];
                ldBk(b, slab, PU, kc, nT + j * 8, lane);
                mma8(ht[0][j], A0, b);
                mma8(ht[1][j], A1, b);
            }
        }
    }
}

__global__ void __launch_bounds__(TPB, 2)
voxel_encoder_kernel(const float* __restrict__ inputs,
                     const float* __restrict__ coordinates,
                     const float* __restrict__ qkv_w,
                     const float* __restrict__ qkv_b,
                     const float* __restrict__ table_x,
                     const float* __restrict__ table_y,
                     const float* __restrict__ table_z,
                     const float* __restrict__ trans_w,
                     const float* __restrict__ trans_b,
                     const float* __restrict__ ln_g,
                     const float* __restrict__ ln_b,
                     const int*   __restrict__ groups,
                     float* __restrict__ out,
                     float* __restrict__ ret)
{
    extern __shared__ __align__(16) char smem_raw[];
    Smem& s = *reinterpret_cast<Smem*>(smem_raw);

    const int tid  = threadIdx.x;
    const int w    = tid >> 5;
    const int lane = tid & 31;
    const int bg   = blockIdx.x;
    const int b    = bg / G_;
    const int g    = bg % G_;
    const int c0   = lane * 4;

    float* XU = s.U1;                 // X lives here (stride PX); P overlays later
    float* P0 = s.U1;                 // P[3][32][56]
    float* P1 = s.U1 + K_ * 56;
    float* P2 = s.U1 + 2 * K_ * 56;

    // ---- gather indices + coordinates ----
    if (tid < K_) {
        int p = groups[bg * K_ + tid];
        s.gidx[tid] = p;
        const float* c = coordinates + ((long long)b * N_ + p) * 3;
        s.cx[tid] = c[0]; s.cy[tid] = c[1]; s.cz[tid] = c[2];
    }
    __syncthreads();

    // ---- gather features into XU [32][PX] ----
#pragma unroll
    for (int rr = 0; rr < 4; rr++) {
        int e = tid + TPB * rr;
        int row = e >> 5, c4 = e & 31;
        *(float4*)&XU[row * PX + c4 * 4] =
            *(const float4*)(inputs + ((long long)b * N_ + s.gidx[row]) * D_ + c4 * 4);
    }
    __syncthreads();

    // ---- trans accumulator in registers: warp w owns cols [16w, 16w+16) ----
    float ht[2][2][4];
#pragma unroll
    for (int j = 0; j < 2; j++) {
        int col = w * 16 + j * 8 + 2 * (lane & 3);
        float b0 = trans_b[col], b1 = trans_b[col + 1];
        ht[0][j][0] = b0; ht[0][j][1] = b1; ht[0][j][2] = b0; ht[0][j][3] = b1;
        ht[1][j][0] = b0; ht[1][j][1] = b1; ht[1][j][2] = b0; ht[1][j][3] = b1;
    }

    // ---- trans block 0 on raw features ----
    trans_mma(XU, s.U2, trans_w, ht, w, lane);

    // ================= attention stages =================
    for (int st = 0; st < S_; st++) {
        // ---------- qkv: C[32][384] = X @ Wq + b ----------
        {
            const float* Wq = qkv_w + (long long)st * D_ * 3 * D_;
            const float* bb = qkv_b + st * 3 * D_;
            const int nw = w * 48;
            float c[2][6][4];
#pragma unroll
            for (int j = 0; j < 6; j++) {
                float b0 = bb[nw + j * 8 + 2 * (lane & 3)];
                float b1 = bb[nw + j * 8 + 2 * (lane & 3) + 1];
                c[0][j][0] = b0; c[0][j][1] = b1; c[0][j][2] = b0; c[0][j][3] = b1;
                c[1][j][0] = b0; c[1][j][1] = b1; c[1][j][2] = b0; c[1][j][3] = b1;
            }
            for (int ch = 0; ch < 8; ch++) {       // 8 chunks of 16 k-rows
                __syncthreads();
                for (int t = tid; t < 16 * 96; t += TPB) {
                    int kk = t / 96, n4 = t % 96;
                    *(float4*)&s.U2[kk * PW + n4 * 4] =
                        *(const float4*)(Wq + (ch * 16 + kk) * 384 + n4 * 4);
                }
                __syncthreads();
#pragma unroll
                for (int k8 = 0; k8 < 2; k8++) {
                    int kc = k8 * 8;
                    u32 a0[4], a1[4];
                    ldA(a0, XU, PX, 0,  ch * 16 + kc, lane);
                    ldA(a1, XU, PX, 16, ch * 16 + kc, lane);
#pragma unroll
                    for (int j = 0; j < 6; j++) {
                        u32 bv[2];
                        ldBk(bv, s.U2, PW, kc, nw + j * 8, lane);
                        mma8(c[0][j], a0, bv);
                        mma8(c[1][j], a1, bv);
                    }
                }
            }
            // writeback: cols 0-127 -> q, 128-255 -> k, 256-383 -> vT (transposed)
#pragma unroll
            for (int m = 0; m < 2; m++)
#pragma unroll
                for (int j = 0; j < 6; j++) {
                    int col = nw + j * 8 + 2 * (lane & 3);
                    int row = (lane >> 2) + m * 16;
                    float* c4 = c[m][j];
                    if (col < 128) {
                        *(ull*)&s.q[row * PX + col]       = pack2(c4[0], c4[1]);
                        *(ull*)&s.q[(row + 8) * PX + col] = pack2(c4[2], c4[3]);
                    } else if (col < 256) {
                        int cc = col - 128;
                        *(ull*)&s.k[row * PX + cc]        = pack2(c4[0], c4[1]);
                        *(ull*)&s.k[(row + 8) * PX + cc]  = pack2(c4[2], c4[3]);
                    } else {
                        int cc = col - 256;
                        s.vT[cc * PT + row]           = c4[0];
                        s.vT[(cc + 1) * PT + row]     = c4[1];
                        s.vT[cc * PT + row + 8]       = c4[2];
                        s.vT[(cc + 1) * PT + row + 8] = c4[3];
                    }
                }
            __syncthreads();
        }

        // ---------- P projections (warps 0-6) + scores (warp 7) ----------
        {
            float pc[3][2][4];
            float scv[4][2][4];
#pragma unroll
            for (int u = 0; u < 3; u++)
#pragma unroll
                for (int m = 0; m < 2; m++)
#pragma unroll
                    for (int r = 0; r < 4; r++) pc[u][m][r] = 0.f;
#pragma unroll
            for (int n = 0; n < 4; n++)
#pragma unroll
                for (int m = 0; m < 2; m++)
#pragma unroll
                    for (int r = 0; r < 4; r++) scv[n][m][r] = 0.f;

            const long long toff = (long long)(st * 3 + 1) * L_ * D_;
            for (int ch = 0; ch < 4; ch++) {       // 4 chunks of 32 d
                __syncthreads();
                for (int t = tid; t < 3 * 56 * 8; t += TPB) {
                    int tb = t / 448, r = t % 448, l = r >> 3, d8 = r & 7;
                    if (l < L_) {
                        const float* tp = (tb == 0 ? table_x : (tb == 1 ? table_y : table_z)) + toff;
                        *(float4*)&s.U2[(tb * 56 + l) * PT + d8 * 4] =
                            *(const float4*)(tp + l * D_ + ch * 32 + d8 * 4);
                    }
                }
                __syncthreads();
                if (w < 7) {
#pragma unroll
                    for (int k8 = 0; k8 < 4; k8++) {
                        int kc = k8 * 8;
                        u32 a0[4], a1[4];
                        ldA(a0, s.k, PX, 0,  ch * 32 + kc, lane);
                        ldA(a1, s.k, PX, 16, ch * 32 + kc, lane);
#pragma unroll
                        for (int u = 0; u < 3; u++) {
                            int tile = w * 3 + u;
                            int tt = tile / 7, nc = (tile % 7) * 8;
                            u32 bv[2];
                            ldBn(bv, s.U2 + tt * 56 * PT, PT, nc, kc, lane);
                            mma8(pc[u][0], a0, bv);
                            mma8(pc[u][1], a1, bv);
                        }
                    }
                } else {
#pragma unroll
                    for (int k8 = 0; k8 < 4; k8++) {
                        int kc = k8 * 8;
                        u32 a0[4], a1[4];
                        ldA(a0, s.q, PX, 0,  ch * 32 + kc, lane);
                        ldA(a1, s.q, PX, 16, ch * 32 + kc, lane);
#pragma unroll
                        for (int n = 0; n < 4; n++) {
                            u32 bv[2];
                            ldBn(bv, s.k, PX, n * 8, ch * 32 + kc, lane);
                            mma8(scv[n][0], a0, bv);
                            mma8(scv[n][1], a1, bv);
                        }
                    }
                }
            }
            // writeback (P overlays X in U1 -- X fully consumed by qkv)
            if (w < 7) {
#pragma unroll
                for (int u = 0; u < 3; u++) {
                    int tile = w * 3 + u;
                    int tt = tile / 7, nc = (tile % 7) * 8;
                    float* Pb = s.U1 + tt * K_ * 56;
#pragma unroll
                    for (int m = 0; m < 2; m++) {
                        int col = nc + 2 * (lane & 3);
                        int row = (lane >> 2) + m * 16;
                        *(ull*)&Pb[row * 56 + col]       = pack2(pc[u][m][0], pc[u][m][1]);
                        *(ull*)&Pb[(row + 8) * 56 + col] = pack2(pc[u][m][2], pc[u][m][3]);
                    }
                }
            } else {
#pragma unroll
                for (int n = 0; n < 4; n++)
#pragma unroll
                    for (int m = 0; m < 2; m++) {
                        int col = n * 8 + 2 * (lane & 3);
                        int row = (lane >> 2) + m * 16;
                        *(ull*)&s.sa[row * PT + col]       = pack2(scv[n][m][0], scv[n][m][1]);
                        *(ull*)&s.sa[(row + 8) * PT + col] = pack2(scv[n][m][2], scv[n][m][3]);
                    }
            }
            __syncthreads();
        }

        // ---------- bias gather + softmax (warp w owns rows 4w..4w+3) ----------
        {
            const int i0 = w * 4;
            float cxj = s.cx[lane], cyj = s.cy[lane], czj = s.cz[lane];
#pragma unroll
            for (int r = 0; r < 4; r++) {
                int i = i0 + r;
                float dx = s.cx[i] - cxj;
                float dy = s.cy[i] - cyj;
                float dz = s.cz[i] - czj;
                int ix = min(max((int)floorf((dx + 0.25f) / 0.01f), 0), L_ - 1);
                int iy = min(max((int)floorf((dy + 0.25f) / 0.01f), 0), L_ - 1);
                int iz = min(max((int)floorf((dz + 0.25f) / 0.01f), 0), L_ - 1);
                float sc = (s.sa[i * PT + lane]
                            + P0[i * 56 + ix] + P1[i * 56 + iy] + P2[i * 56 + iz])
                           * 0.08838834764831843f;    // 1/sqrt(128)
                float mx = sc;
#pragma unroll
                for (int o = 16; o; o >>= 1) mx = fmaxf(mx, __shfl_xor_sync(0xffffffffu, mx, o));
                float e = __expf(sc - mx);
                float sum = e;
#pragma unroll
                for (int o = 16; o; o >>= 1) sum += __shfl_xor_sync(0xffffffffu, sum, o);
                s.sa[i * PT + lane] = e * (1.0f / sum);
            }
        }
        __syncthreads();

        // ---------- f = attn @ v : A=sa[32][36], B=vT[128][36] ----------
        {
            float fc[2][2][4];
#pragma unroll
            for (int m = 0; m < 2; m++)
#pragma unroll
                for (int j = 0; j < 2; j++)
#pragma unroll
                    for (int r = 0; r < 4; r++) fc[m][j][r] = 0.f;
#pragma unroll
            for (int k8 = 0; k8 < 4; k8++) {
                int kc = k8 * 8;
                u32 a0[4], a1[4];
                ldA(a0, s.sa, PT, 0,  kc, lane);
                ldA(a1, s.sa, PT, 16, kc, lane);
#pragma unroll
                for (int j = 0; j < 2; j++) {
                    int nc = w * 16 + j * 8;
                    u32 bv[2];
                    ldBn(bv, s.vT, PT, nc, kc, lane);
                    mma8(fc[0][j], a0, bv);
                    mma8(fc[1][j], a1, bv);
                }
            }
            // FO -> U1 (P dead after softmax); becomes next-stage X
#pragma unroll
            for (int m = 0; m < 2; m++)
#pragma unroll
                for (int j = 0; j < 2; j++) {
                    int col = w * 16 + j * 8 + 2 * (lane & 3);
                    int row = (lane >> 2) + m * 16;
                    *(ull*)&XU[row * PX + col]       = pack2(fc[m][j][0], fc[m][j][1]);
                    *(ull*)&XU[(row + 8) * PX + col] = pack2(fc[m][j][2], fc[m][j][3]);
                }
        }
        __syncthreads();

        // ---------- trans block st+1 ----------
        trans_mma(XU, s.U2, trans_w + (st + 1) * D_ * D_, ht, w, lane);
        __syncthreads();
    }

    // ---- dump trans accumulator to smem (q region is free) ----
#pragma unroll
    for (int m = 0; m < 2; m++)
#pragma unroll
        for (int j = 0; j < 2; j++) {
            int col = w * 16 + j * 8 + 2 * (lane & 3);
            int row = (lane >> 2) + m * 16;
            *(ull*)&s.q[row * PX + col]       = pack2(ht[m][j][0], ht[m][j][1]);
            *(ull*)&s.q[(row + 8) * PX + col] = pack2(ht[m][j][2], ht[m][j][3]);
        }
    __syncthreads();

    // ================= LayerNorm + ReLU (rows 4w..4w+3) =================
    {
        const int i0 = w * 4;
        float4 g4 = *(const float4*)(ln_g + c0);
        float4 b4 = *(const float4*)(ln_b + c0);
#pragma unroll
        for (int r = 0; r < 4; r++) {
            int i = i0 + r;
            float4 h = *(const float4*)&s.q[i * PX + c0];
            float s1 = h.x + h.y + h.z + h.w;
            float s2 = h.x * h.x + h.y * h.y + h.z * h.z + h.w * h.w;
#pragma unroll
            for (int o = 16; o; o >>= 1) {
                s1 += __shfl_xor_sync(0xffffffffu, s1, o);
                s2 += __shfl_xor_sync(0xffffffffu, s2, o);
            }
            float mu   = s1 * (1.0f / 128.0f);
            float var  = s2 * (1.0f / 128.0f) - mu * mu;
            float rstd = rsqrtf(var + 1e-5f);
            h.x = fmaxf((h.x - mu) * rstd * g4.x + b4.x, 0.0f);
            h.y = fmaxf((h.y - mu) * rstd * g4.y + b4.y, 0.0f);
            h.z = fmaxf((h.z - mu) * rstd * g4.z + b4.z, 0.0f);
            h.w = fmaxf((h.w - mu) * rstd * g4.w + b4.w, 0.0f);
            *(float4*)&s.q[i * PX + c0] = h;
        }
    }
    __syncthreads();

    // ================= max-pool + outputs =================
    if (tid < D_) {
        float m = s.q[tid];
#pragma unroll
        for (int i = 1; i < K_; i++) m = fmaxf(m, s.q[i * PX + tid]);
        s.pooled[tid] = m;
        int mm = g >> 6, nn = (g >> 3) & 7, tt = g & 7;
        int p = (tt << 6) + (nn << 3) + mm;          // transpose(0,3,2,1,4)
        out[((long long)b * G_ + p) * D_ + tid] = m;
    }
    __syncthreads();

#pragma unroll
    for (int rr = 0; rr < 4; rr++) {
        int e = tid + TPB * rr;
        int row = e >> 5, c4 = e & 31;
        float4 val = *(const float4*)&s.pooled[c4 * 4];
        *(float4*)(ret + ((long long)b * N_ + s.gidx[row]) * D_ + c4 * 4) = val;
    }
}

extern "C" void kernel_launch(void* const* d_in, const int* in_sizes, int n_in,
                              void* d_out, int out_size)
{
    const float* inputs      = (const float*)d_in[0];
    const float* coordinates = (const float*)d_in[1];
    const float* qkv_w       = (const float*)d_in[2];
    const float* qkv_b       = (const float*)d_in[3];
    const float* table_x     = (const float*)d_in[4];
    const float* table_y     = (const float*)d_in[5];
    const float* table_z     = (const float*)d_in[6];
    const float* trans_w     = (const float*)d_in[7];
    const float* trans_b     = (const float*)d_in[8];
    const float* ln_g        = (const float*)d_in[9];
    const float* ln_b        = (const float*)d_in[10];
    const int*   groups      = (const int*)d_in[11];

    float* out = (float*)d_out;                      // [B, 512, 128]
    float* ret = out + (size_t)B_ * G_ * D_;         // [B, 16384, 128]

    cudaFuncSetAttribute(voxel_encoder_kernel,
                         cudaFuncAttributeMaxDynamicSharedMemorySize,
                         (int)sizeof(Smem));

    voxel_encoder_kernel<<<B_ * G_, TPB, sizeof(Smem)>>>(
        inputs, coordinates, qkv_w, qkv_b, table_x, table_y, table_z,
        trans_w, trans_b, ln_g, ln_b, groups, out, ret);
}

// round 4
// speedup vs baseline: 3.5366x; 1.5678x over previous
#include <cuda_runtime.h>

#define B_   2
#define G_   512
#define K_   32
#define D_   128
#define N_   16384
#define L_   50
#define S_   2
#define TPB  256
#define PX   132     // stride for 32x128 tiles (conflict-free frag loads)
#define PT   36      // stride for vT / sa

typedef unsigned long long ull;
typedef unsigned int u32;

__device__ __forceinline__ ull pack2(float x, float y) {
    ull r; asm("mov.b64 %0, {%1, %2};" : "=l"(r) : "f"(x), "f"(y)); return r;
}
__device__ __forceinline__ u32 tf(float x) {
    u32 r; asm("cvt.rna.tf32.f32 %0, %1;" : "=r"(r) : "f"(x)); return r;
}
__device__ __forceinline__ float tff(float x) { return __uint_as_float(tf(x)); }
__device__ __forceinline__ ull pack2t(float x, float y) { return pack2(tff(x), tff(y)); }

__device__ __forceinline__ void mma8(float* c, const u32* a, const u32* b) {
    asm("mma.sync.aligned.m16n8k8.row.col.f32.tf32.tf32.f32 "
        "{%0,%1,%2,%3},{%4,%5,%6,%7},{%8,%9},{%0,%1,%2,%3};"
        : "+f"(c[0]), "+f"(c[1]), "+f"(c[2]), "+f"(c[3])
        : "r"(a[0]), "r"(a[1]), "r"(a[2]), "r"(a[3]), "r"(b[0]), "r"(b[1]));
}

// raw (pre-converted tf32 bits) A fragment from smem, row-major
__device__ __forceinline__ void ldAr(u32* a, const float* S, int stride, int mr, int kc, int lane) {
    const u32* p = (const u32*)S + (mr + (lane >> 2)) * stride + kc + (lane & 3);
    a[0] = p[0]; a[1] = p[8 * stride]; a[2] = p[4]; a[3] = p[8 * stride + 4];
}
// raw B fragment from n-major smem: B[k][n] at S[n*stride + k]
__device__ __forceinline__ void ldBnr(u32* b, const float* S, int stride, int nc, int kc, int lane) {
    const u32* p = (const u32*)S + (nc + (lane >> 2)) * stride + kc + (lane & 3);
    b[0] = p[0]; b[1] = p[4];
}
// B fragment from k-major GMEM (weights): B[k][n] at W[k*ldw + n], cvt here
__device__ __forceinline__ void ldBkG(u32* b, const float* __restrict__ W, int ldw,
                                      int kc, int nc, int lane) {
    const float* p = W + (kc + (lane & 3)) * ldw + nc + (lane >> 2);
    b[0] = tf(p[0]); b[1] = tf(p[4 * ldw]);
}
// B fragment from n-major GMEM (tables): B[k][n] at T[n*ld + k], cvt here
__device__ __forceinline__ void ldBnG(u32* b, const float* __restrict__ T, int ld,
                                      int nc, int kc, int lane) {
    const float* p = T + (nc + (lane >> 2)) * ld + kc + (lane & 3);
    b[0] = tf(p[0]); b[1] = tf(p[4]);
}

// ---------------- shared memory (~80 KB -> 2 CTAs/SM) ----------------
struct __align__(16) Smem {
    float U1[3 * K_ * 56];   // X(tf32)[32][132] UNION P[3][32][56] UNION FO
    float q [K_ * PX];       // tf32 bits
    float k [K_ * PX];       // tf32 bits
    float vT[D_ * PT];       // v transposed, tf32 bits
    float sa[K_ * PT];       // float scores -> tf32 attn
    float cx[K_], cy[K_], cz[K_];
    float pooled[D_];
    int   gidx[K_];
};

// ht += X @ W (128x128 k-major gmem block); warp w owns cols [16w,16w+16)
__device__ __forceinline__ void trans_mma(const float* __restrict__ X,
                                          const float* __restrict__ W,
                                          float ht[2][2][4], int w, int lane)
{
    const int nT = w * 16;
#pragma unroll 4
    for (int k8 = 0; k8 < 16; k8++) {
        const int kc = k8 * 8;
        u32 b0[2], b1[2];
        ldBkG(b0, W, D_, kc, nT, lane);
        ldBkG(b1, W, D_, kc, nT + 8, lane);
        u32 a0[4], a1[4];
        ldAr(a0, X, PX, 0,  kc, lane);
        ldAr(a1, X, PX, 16, kc, lane);
        mma8(ht[0][0], a0, b0); mma8(ht[1][0], a1, b0);
        mma8(ht[0][1], a0, b1); mma8(ht[1][1], a1, b1);
    }
}

__global__ void __launch_bounds__(TPB, 2)
voxel_encoder_kernel(const float* __restrict__ inputs,
                     const float* __restrict__ coordinates,
                     const float* __restrict__ qkv_w,
                     const float* __restrict__ qkv_b,
                     const float* __restrict__ table_x,
                     const float* __restrict__ table_y,
                     const float* __restrict__ table_z,
                     const float* __restrict__ trans_w,
                     const float* __restrict__ trans_b,
                     const float* __restrict__ ln_g,
                     const float* __restrict__ ln_b,
                     const int*   __restrict__ groups,
                     float* __restrict__ out,
                     float* __restrict__ ret)
{
    extern __shared__ __align__(16) char smem_raw[];
    Smem& s = *reinterpret_cast<Smem*>(smem_raw);

    const int tid  = threadIdx.x;
    const int w    = tid >> 5;
    const int lane = tid & 31;
    const int bg   = blockIdx.x;
    const int b    = bg / G_;
    const int g    = bg % G_;
    const int c0   = lane * 4;

    float* XU = s.U1;
    float* P0 = s.U1;
    float* P1 = s.U1 + K_ * 56;
    float* P2 = s.U1 + 2 * K_ * 56;

    // ---- gather indices + coordinates ----
    if (tid < K_) {
        int p = groups[bg * K_ + tid];
        s.gidx[tid] = p;
        const float* c = coordinates + ((long long)b * N_ + p) * 3;
        s.cx[tid] = c[0]; s.cy[tid] = c[1]; s.cz[tid] = c[2];
    }
    __syncthreads();

    // ---- gather features -> XU as tf32 bits ----
#pragma unroll
    for (int rr = 0; rr < 4; rr++) {
        int e = tid + TPB * rr;
        int row = e >> 5, c4 = e & 31;
        float4 val = *(const float4*)(inputs + ((long long)b * N_ + s.gidx[row]) * D_ + c4 * 4);
        val.x = tff(val.x); val.y = tff(val.y); val.z = tff(val.z); val.w = tff(val.w);
        *(float4*)&XU[row * PX + c4 * 4] = val;
    }
    __syncthreads();

    // ---- trans accumulator in registers: warp w cols [16w,16w+16) ----
    float ht[2][2][4];
#pragma unroll
    for (int j = 0; j < 2; j++) {
        int col = w * 16 + j * 8 + 2 * (lane & 3);
        float b0 = trans_b[col], b1 = trans_b[col + 1];
        ht[0][j][0] = b0; ht[0][j][1] = b1; ht[0][j][2] = b0; ht[0][j][3] = b1;
        ht[1][j][0] = b0; ht[1][j][1] = b1; ht[1][j][2] = b0; ht[1][j][3] = b1;
    }

    trans_mma(XU, trans_w, ht, w, lane);     // block 0 on raw features

    // ================= attention stages =================
    for (int st = 0; st < S_; st++) {
        // ---------- qkv: C[32][384] = X @ Wq + b; warp w cols [48w,48w+48) ----------
        {
            const float* Wq = qkv_w + (long long)st * D_ * 3 * D_;
            const float* bb = qkv_b + st * 3 * D_;
            const int nw = w * 48;
            float c[2][6][4];
#pragma unroll
            for (int j = 0; j < 6; j++) {
                float b0 = bb[nw + j * 8 + 2 * (lane & 3)];
                float b1 = bb[nw + j * 8 + 2 * (lane & 3) + 1];
                c[0][j][0] = b0; c[0][j][1] = b1; c[0][j][2] = b0; c[0][j][3] = b1;
                c[1][j][0] = b0; c[1][j][1] = b1; c[1][j][2] = b0; c[1][j][3] = b1;
            }
#pragma unroll 2
            for (int k8 = 0; k8 < 16; k8++) {
                const int kc = k8 * 8;
                u32 bv[6][2];
#pragma unroll
                for (int j = 0; j < 6; j++) ldBkG(bv[j], Wq, 384, kc, nw + j * 8, lane);
                u32 a0[4], a1[4];
                ldAr(a0, XU, PX, 0,  kc, lane);
                ldAr(a1, XU, PX, 16, kc, lane);
#pragma unroll
                for (int j = 0; j < 6; j++) {
                    mma8(c[0][j], a0, bv[j]);
                    mma8(c[1][j], a1, bv[j]);
                }
            }
            // writeback (tf32 bits): cols 0-127 -> q, 128-255 -> k, 256-383 -> vT
#pragma unroll
            for (int m = 0; m < 2; m++)
#pragma unroll
                for (int j = 0; j < 6; j++) {
                    int col = nw + j * 8 + 2 * (lane & 3);
                    int row = (lane >> 2) + m * 16;
                    float* c4 = c[m][j];
                    if (col < 128) {
                        *(ull*)&s.q[row * PX + col]       = pack2t(c4[0], c4[1]);
                        *(ull*)&s.q[(row + 8) * PX + col] = pack2t(c4[2], c4[3]);
                    } else if (col < 256) {
                        int cc = col - 128;
                        *(ull*)&s.k[row * PX + cc]        = pack2t(c4[0], c4[1]);
                        *(ull*)&s.k[(row + 8) * PX + cc]  = pack2t(c4[2], c4[3]);
                    } else {
                        int cc = col - 256;
                        s.vT[cc * PT + row]           = tff(c4[0]);
                        s.vT[(cc + 1) * PT + row]     = tff(c4[1]);
                        s.vT[cc * PT + row + 8]       = tff(c4[2]);
                        s.vT[(cc + 1) * PT + row + 8] = tff(c4[3]);
                    }
                }
            __syncthreads();
        }

        // ---------- P projections (warps 0-6, tables direct from gmem) + scores (warp 7) ----------
        {
            const long long toff = (long long)(st * 3 + 1) * L_ * D_;
            if (w < 7) {
                const float* Tp[3]; int ncs[3];
#pragma unroll
                for (int u = 0; u < 3; u++) {
                    int tile = w * 3 + u;
                    int tt = tile / 7; ncs[u] = (tile % 7) * 8;
                    Tp[u] = (tt == 0 ? table_x : (tt == 1 ? table_y : table_z)) + toff;
                }
                float pc[3][2][4];
#pragma unroll
                for (int u = 0; u < 3; u++)
#pragma unroll
                    for (int m = 0; m < 2; m++)
#pragma unroll
                        for (int r = 0; r < 4; r++) pc[u][m][r] = 0.f;
#pragma unroll 2
                for (int k8 = 0; k8 < 16; k8++) {
                    const int kc = k8 * 8;
                    u32 bv[3][2];
#pragma unroll
                    for (int u = 0; u < 3; u++) ldBnG(bv[u], Tp[u], D_, ncs[u], kc, lane);
                    u32 a0[4], a1[4];
                    ldAr(a0, s.k, PX, 0,  kc, lane);
                    ldAr(a1, s.k, PX, 16, kc, lane);
#pragma unroll
                    for (int u = 0; u < 3; u++) {
                        mma8(pc[u][0], a0, bv[u]);
                        mma8(pc[u][1], a1, bv[u]);
                    }
                }
#pragma unroll
                for (int u = 0; u < 3; u++) {
                    int tile = w * 3 + u;
                    int tt = tile / 7, nc = (tile % 7) * 8;
                    float* Pb = s.U1 + tt * K_ * 56;
#pragma unroll
                    for (int m = 0; m < 2; m++) {
                        int col = nc + 2 * (lane & 3);
                        int row = (lane >> 2) + m * 16;
                        *(ull*)&Pb[row * 56 + col]       = pack2(pc[u][m][0], pc[u][m][1]);
                        *(ull*)&Pb[(row + 8) * 56 + col] = pack2(pc[u][m][2], pc[u][m][3]);
                    }
                }
            } else {
                float scv[4][2][4];
#pragma unroll
                for (int n = 0; n < 4; n++)
#pragma unroll
                    for (int m = 0; m < 2; m++)
#pragma unroll
                        for (int r = 0; r < 4; r++) scv[n][m][r] = 0.f;
#pragma unroll 2
                for (int k8 = 0; k8 < 16; k8++) {
                    const int kc = k8 * 8;
                    u32 a0[4], a1[4];
                    ldAr(a0, s.q, PX, 0,  kc, lane);
                    ldAr(a1, s.q, PX, 16, kc, lane);
#pragma unroll
                    for (int n = 0; n < 4; n++) {
                        u32 bv[2];
                        ldBnr(bv, s.k, PX, n * 8, kc, lane);
                        mma8(scv[n][0], a0, bv);
                        mma8(scv[n][1], a1, bv);
                    }
                }
#pragma unroll
                for (int n = 0; n < 4; n++)
#pragma unroll
                    for (int m = 0; m < 2; m++) {
                        int col = n * 8 + 2 * (lane & 3);
                        int row = (lane >> 2) + m * 16;
                        *(ull*)&s.sa[row * PT + col]       = pack2(scv[n][m][0], scv[n][m][1]);
                        *(ull*)&s.sa[(row + 8) * PT + col] = pack2(scv[n][m][2], scv[n][m][3]);
                    }
            }
            __syncthreads();
        }

        // ---------- bias gather + softmax (warp w rows 4w..4w+3) ----------
        {
            const int i0 = w * 4;
            float cxj = s.cx[lane], cyj = s.cy[lane], czj = s.cz[lane];
#pragma unroll
            for (int r = 0; r < 4; r++) {
                int i = i0 + r;
                float dx = s.cx[i] - cxj;
                float dy = s.cy[i] - cyj;
                float dz = s.cz[i] - czj;
                int ix = min(max((int)floorf((dx + 0.25f) / 0.01f), 0), L_ - 1);
                int iy = min(max((int)floorf((dy + 0.25f) / 0.01f), 0), L_ - 1);
                int iz = min(max((int)floorf((dz + 0.25f) / 0.01f), 0), L_ - 1);
                float sc = (s.sa[i * PT + lane]
                            + P0[i * 56 + ix] + P1[i * 56 + iy] + P2[i * 56 + iz])
                           * 0.08838834764831843f;
                float mx = sc;
#pragma unroll
                for (int o = 16; o; o >>= 1) mx = fmaxf(mx, __shfl_xor_sync(0xffffffffu, mx, o));
                float e = __expf(sc - mx);
                float sum = e;
#pragma unroll
                for (int o = 16; o; o >>= 1) sum += __shfl_xor_sync(0xffffffffu, sum, o);
                s.sa[i * PT + lane] = tff(e * (1.0f / sum));   // tf32 bits for mma
            }
        }
        __syncthreads();

        // ---------- f = attn @ v : A=sa[32][36] B=vT(n-major) ----------
        {
            float fc[2][2][4];
#pragma unroll
            for (int m = 0; m < 2; m++)
#pragma unroll
                for (int j = 0; j < 2; j++)
#pragma unroll
                    for (int r = 0; r < 4; r++) fc[m][j][r] = 0.f;
#pragma unroll
            for (int k8 = 0; k8 < 4; k8++) {
                int kc = k8 * 8;
                u32 a0[4], a1[4];
                ldAr(a0, s.sa, PT, 0,  kc, lane);
                ldAr(a1, s.sa, PT, 16, kc, lane);
#pragma unroll
                for (int j = 0; j < 2; j++) {
                    u32 bv[2];
                    ldBnr(bv, s.vT, PT, w * 16 + j * 8, kc, lane);
                    mma8(fc[0][j], a0, bv);
                    mma8(fc[1][j], a1, bv);
                }
            }
            // FO -> U1 as tf32 bits (P dead after softmax); next-stage X
#pragma unroll
            for (int m = 0; m < 2; m++)
#pragma unroll
                for (int j = 0; j < 2; j++) {
                    int col = w * 16 + j * 8 + 2 * (lane & 3);
                    int row = (lane >> 2) + m * 16;
                    *(ull*)&XU[row * PX + col]       = pack2t(fc[m][j][0], fc[m][j][1]);
                    *(ull*)&XU[(row + 8) * PX + col] = pack2t(fc[m][j][2], fc[m][j][3]);
                }
        }
        __syncthreads();

        // ---------- trans block st+1 (gmem weights, reg accum, no syncs) ----------
        trans_mma(XU, trans_w + (st + 1) * D_ * D_, ht, w, lane);
        __syncthreads();
    }

    // ---- dump trans accumulator (float) to s.q ----
#pragma unroll
    for (int m = 0; m < 2; m++)
#pragma unroll
        for (int j = 0; j < 2; j++) {
            int col = w * 16 + j * 8 + 2 * (lane & 3);
            int row = (lane >> 2) + m * 16;
            *(ull*)&s.q[row * PX + col]       = pack2(ht[m][j][0], ht[m][j][1]);
            *(ull*)&s.q[(row + 8) * PX + col] = pack2(ht[m][j][2], ht[m][j][3]);
        }
    __syncthreads();

    // ================= LayerNorm + ReLU =================
    {
        const int i0 = w * 4;
        float4 g4 = *(const float4*)(ln_g + c0);
        float4 b4 = *(const float4*)(ln_b + c0);
#pragma unroll
        for (int r = 0; r < 4; r++) {
            int i = i0 + r;
            float4 h = *(const float4*)&s.q[i * PX + c0];
            float s1 = h.x + h.y + h.z + h.w;
            float s2 = h.x * h.x + h.y * h.y + h.z * h.z + h.w * h.w;
#pragma unroll
            for (int o = 16; o; o >>= 1) {
                s1 += __shfl_xor_sync(0xffffffffu, s1, o);
                s2 += __shfl_xor_sync(0xffffffffu, s2, o);
            }
            float mu   = s1 * (1.0f / 128.0f);
            float var  = s2 * (1.0f / 128.0f) - mu * mu;
            float rstd = rsqrtf(var + 1e-5f);
            h.x = fmaxf((h.x - mu) * rstd * g4.x + b4.x, 0.0f);
            h.y = fmaxf((h.y - mu) * rstd * g4.y + b4.y, 0.0f);
            h.z = fmaxf((h.z - mu) * rstd * g4.z + b4.z, 0.0f);
            h.w = fmaxf((h.w - mu) * rstd * g4.w + b4.w, 0.0f);
            *(float4*)&s.q[i * PX + c0] = h;
        }
    }
    __syncthreads();

    // ================= max-pool + outputs =================
    if (tid < D_) {
        float m = s.q[tid];
#pragma unroll
        for (int i = 1; i < K_; i++) m = fmaxf(m, s.q[i * PX + tid]);
        s.pooled[tid] = m;
        int mm = g >> 6, nn = (g >> 3) & 7, tt = g & 7;
        int p = (tt << 6) + (nn << 3) + mm;          // transpose(0,3,2,1,4)
        out[((long long)b * G_ + p) * D_ + tid] = m;
    }
    __syncthreads();

#pragma unroll
    for (int rr = 0; rr < 4; rr++) {
        int e = tid + TPB * rr;
        int row = e >> 5, c4 = e & 31;
        float4 val = *(const float4*)&s.pooled[c4 * 4];
        *(float4*)(ret + ((long long)b * N_ + s.gidx[row]) * D_ + c4 * 4) = val;
    }
}

extern "C" void kernel_launch(void* const* d_in, const int* in_sizes, int n_in,
                              void* d_out, int out_size)
{
    const float* inputs      = (const float*)d_in[0];
    const float* coordinates = (const float*)d_in[1];
    const float* qkv_w       = (const float*)d_in[2];
    const float* qkv_b       = (const float*)d_in[3];
    const float* table_x     = (const float*)d_in[4];
    const float* table_y     = (const float*)d_in[5];
    const float* table_z     = (const float*)d_in[6];
    const float* trans_w     = (const float*)d_in[7];
    const float* trans_b     = (const float*)d_in[8];
    const float* ln_g        = (const float*)d_in[9];
    const float* ln_b        = (const float*)d_in[10];
    const int*   groups      = (const int*)d_in[11];

    float* out = (float*)d_out;                      // [B, 512, 128]
    float* ret = out + (size_t)B_ * G_ * D_;         // [B, 16384, 128]

    cudaFuncSetAttribute(voxel_encoder_kernel,
                         cudaFuncAttributeMaxDynamicSharedMemorySize,
                         (int)sizeof(Smem));

    voxel_encoder_kernel<<<B_ * G_, TPB, sizeof(Smem)>>>(
        inputs, coordinates, qkv_w, qkv_b, table_x, table_y, table_z,
        trans_w, trans_b, ln_g, ln_b, groups, out, ret);
}

// round 5
// speedup vs baseline: 5.5502x; 1.5693x over previous
#include <cuda_runtime.h>

#define B_   2
#define G_   512
#define K_   32
#define D_   128
#define N_   16384
#define L_   50
#define S_   2
#define TPB  256
#define PX   132     // stride for 32x128 tiles (conflict-free frag loads)
#define PT   36      // stride for vT / sa

typedef unsigned long long ull;
typedef unsigned int u32;

// fragment-order repacked weights (tf32 bits), written by repack_kernel each launch
__device__ u32 qkvR[2 * 16 * 8 * 3 * 128];   // [st][k8][w][jp][128]  = 98304
__device__ u32 trR [3 * 16 * 8 * 128];       // [blk][k8][w][128]     = 49152
__device__ u32 tbR [2 * 3 * 16 * 7 * 64];    // [st][t][k8][n][64]    = 43008

__device__ __forceinline__ ull pack2(float x, float y) {
    ull r; asm("mov.b64 %0, {%1, %2};" : "=l"(r) : "f"(x), "f"(y)); return r;
}
__device__ __forceinline__ u32 tf(float x) {
    u32 r; asm("cvt.rna.tf32.f32 %0, %1;" : "=r"(r) : "f"(x)); return r;
}
__device__ __forceinline__ float tff(float x) { return __uint_as_float(tf(x)); }
__device__ __forceinline__ ull pack2t(float x, float y) { return pack2(tff(x), tff(y)); }

__device__ __forceinline__ void mma8(float* c, const u32* a, const u32* b) {
    asm("mma.sync.aligned.m16n8k8.row.col.f32.tf32.tf32.f32 "
        "{%0,%1,%2,%3},{%4,%5,%6,%7},{%8,%9},{%0,%1,%2,%3};"
        : "+f"(c[0]), "+f"(c[1]), "+f"(c[2]), "+f"(c[3])
        : "r"(a[0]), "r"(a[1]), "r"(a[2]), "r"(a[3]), "r"(b[0]), "r"(b[1]));
}

// raw tf32-bit A fragment from smem, row-major
__device__ __forceinline__ void ldAr(u32* a, const float* S, int stride, int mr, int kc, int lane) {
    const u32* p = (const u32*)S + (mr + (lane >> 2)) * stride + kc + (lane & 3);
    a[0] = p[0]; a[1] = p[8 * stride]; a[2] = p[4]; a[3] = p[8 * stride + 4];
}
// raw B fragment from n-major smem: B[k][n] at S[n*stride + k]
__device__ __forceinline__ void ldBnr(u32* b, const float* S, int stride, int nc, int kc, int lane) {
    const u32* p = (const u32*)S + (nc + (lane >> 2)) * stride + kc + (lane & 3);
    b[0] = p[0]; b[1] = p[4];
}

// ---------------- repack kernel: gmem weights -> fragment-order tf32 ----------------
// qkvR element e: l=e&127: lane=l>>2, j2=(l>>1)&1, h=l&1; f=e>>7: jp=f%3, w=(f/3)%8,
//                 k8=(f/24)%16, st=f/384;  j=jp*2+j2
// trR  element e: l=e&127: lane=l>>2, j=(l>>1)&1, h=l&1; f=e>>7: w=f%8, k8=(f/8)%16, blk=f/128
// tbR  element e: l=e&63:  lane=l>>1, h=l&1;  f=e>>6: n=f%7, k8=(f/7)%16, t=(f/112)%3, st=f/336
__global__ void repack_kernel(const float* __restrict__ qkv_w,
                              const float* __restrict__ trans_w,
                              const float* __restrict__ tx,
                              const float* __restrict__ ty,
                              const float* __restrict__ tz)
{
    int e = blockIdx.x * TPB + threadIdx.x;
    if (e < 98304) {
        int l = e & 127, lane = l >> 2, j2 = (l >> 1) & 1, h = l & 1;
        int f = e >> 7;
        int jp = f % 3; f /= 3;
        int w  = f % 8; f /= 8;
        int k8 = f % 16;
        int st = f / 16;
        int j   = jp * 2 + j2;
        int row = k8 * 8 + (lane & 3) + h * 4;
        int col = w * 48 + j * 8 + (lane >> 2);
        qkvR[e] = tf(qkv_w[st * 49152 + row * 384 + col]);
    } else if (e < 147456) {
        int e2 = e - 98304;
        int l = e2 & 127, lane = l >> 2, j = (l >> 1) & 1, h = l & 1;
        int f = e2 >> 7;
        int w   = f % 8; f /= 8;
        int k8  = f % 16;
        int blk = f / 16;
        int row = k8 * 8 + (lane & 3) + h * 4;
        int col = w * 16 + j * 8 + (lane >> 2);
        trR[e2] = tf(trans_w[blk * 16384 + row * 128 + col]);
    } else if (e < 190464) {
        int e2 = e - 147456;
        int l = e2 & 63, lane = l >> 1, h = l & 1;
        int f = e2 >> 6;
        int n  = f % 7;  f /= 7;
        int k8 = f % 16; f /= 16;
        int t  = f % 3;
        int st = f / 3;
        const float* T = (t == 0 ? tx : (t == 1 ? ty : tz)) + (st * 3 + 1) * L_ * D_;
        int nn = n * 8 + (lane >> 2);      // up to 55: in-bounds of table allocation
        int kk = k8 * 8 + (lane & 3) + h * 4;
        tbR[e2] = tf(T[nn * D_ + kk]);
    }
}

// ---------------- shared memory (~84 KB -> 2 CTAs/SM) ----------------
struct __align__(16) Smem {
    float U1[3 * K_ * 56];   // X(tf32)[32][132] UNION P[3][32][56] UNION FO
    float q [K_ * PX];       // tf32 bits
    float k [K_ * PX];       // tf32 bits
    float vT[D_ * PT];       // v transposed, tf32 bits
    float sa[K_ * PT];       // float scores -> tf32 attn
    int   idxp[K_][K_];      // packed quant indices (stage 0 -> stage 1)
    float cx[K_], cy[K_], cz[K_];
    float pooled[D_];
    int   gidx[K_];
};

// ht += X @ W-block (repacked); warp w owns cols [16w,16w+16)
__device__ __forceinline__ void trans_mma(const float* __restrict__ X,
                                          const u32* __restrict__ Rblk,
                                          float ht[2][2][4], int w, int lane)
{
#pragma unroll 4
    for (int k8 = 0; k8 < 16; k8++) {
        uint4 vv = *(const uint4*)&Rblk[((k8 * 8 + w) << 7) + lane * 4];
        u32 b0[2] = {vv.x, vv.y}, b1[2] = {vv.z, vv.w};
        u32 a0[4], a1[4];
        ldAr(a0, X, PX, 0,  k8 * 8, lane);
        ldAr(a1, X, PX, 16, k8 * 8, lane);
        mma8(ht[0][0], a0, b0); mma8(ht[1][0], a1, b0);
        mma8(ht[0][1], a0, b1); mma8(ht[1][1], a1, b1);
    }
}

__global__ void __launch_bounds__(TPB, 2)
voxel_encoder_kernel(const float* __restrict__ inputs,
                     const float* __restrict__ coordinates,
                     const float* __restrict__ qkv_b,
                     const float* __restrict__ trans_b,
                     const float* __restrict__ ln_g,
                     const float* __restrict__ ln_b,
                     const int*   __restrict__ groups,
                     float* __restrict__ out,
                     float* __restrict__ ret)
{
    extern __shared__ __align__(16) char smem_raw[];
    Smem& s = *reinterpret_cast<Smem*>(smem_raw);

    const int tid  = threadIdx.x;
    const int w    = tid >> 5;
    const int lane = tid & 31;
    const int bg   = blockIdx.x;
    const int b    = bg / G_;
    const int g    = bg % G_;
    const int c0   = lane * 4;

    float* XU = s.U1;
    float* P0 = s.U1;
    float* P1 = s.U1 + K_ * 56;
    float* P2 = s.U1 + 2 * K_ * 56;

    // ---- gather indices + coordinates ----
    if (tid < K_) {
        int p = groups[bg * K_ + tid];
        s.gidx[tid] = p;
        const float* c = coordinates + ((long long)b * N_ + p) * 3;
        s.cx[tid] = c[0]; s.cy[tid] = c[1]; s.cz[tid] = c[2];
    }
    __syncthreads();

    // ---- gather features -> XU as tf32 bits ----
#pragma unroll
    for (int rr = 0; rr < 4; rr++) {
        int e = tid + TPB * rr;
        int row = e >> 5, c4 = e & 31;
        float4 val = *(const float4*)(inputs + ((long long)b * N_ + s.gidx[row]) * D_ + c4 * 4);
        val.x = tff(val.x); val.y = tff(val.y); val.z = tff(val.z); val.w = tff(val.w);
        *(float4*)&XU[row * PX + c4 * 4] = val;
    }
    __syncthreads();

    // ---- trans accumulator in registers: warp w cols [16w,16w+16) ----
    float ht[2][2][4];
#pragma unroll
    for (int j = 0; j < 2; j++) {
        int col = w * 16 + j * 8 + 2 * (lane & 3);
        float b0 = trans_b[col], b1 = trans_b[col + 1];
        ht[0][j][0] = b0; ht[0][j][1] = b1; ht[0][j][2] = b0; ht[0][j][3] = b1;
        ht[1][j][0] = b0; ht[1][j][1] = b1; ht[1][j][2] = b0; ht[1][j][3] = b1;
    }

    trans_mma(XU, trR, ht, w, lane);     // block 0 on raw features

    // ================= attention stages =================
    for (int st = 0; st < S_; st++) {
        // ---------- qkv: C[32][384] = X @ Wq + b; warp w cols [48w,48w+48) ----------
        {
            const float* bb = qkv_b + st * 3 * D_;
            const int nw = w * 48;
            float c[2][6][4];
#pragma unroll
            for (int j = 0; j < 6; j++) {
                float b0 = bb[nw + j * 8 + 2 * (lane & 3)];
                float b1 = bb[nw + j * 8 + 2 * (lane & 3) + 1];
                c[0][j][0] = b0; c[0][j][1] = b1; c[0][j][2] = b0; c[0][j][3] = b1;
                c[1][j][0] = b0; c[1][j][1] = b1; c[1][j][2] = b0; c[1][j][3] = b1;
            }
            const u32* Rq = qkvR + ((st * 16 * 8 + w) * 3) * 128;   // + k8*8*3*128
#pragma unroll 2
            for (int k8 = 0; k8 < 16; k8++) {
                u32 bv[6][2];
#pragma unroll
                for (int jp = 0; jp < 3; jp++) {
                    uint4 vv = *(const uint4*)&Rq[((k8 * 8 * 3 + jp) << 7) + lane * 4];
                    bv[2 * jp][0] = vv.x; bv[2 * jp][1] = vv.y;
                    bv[2 * jp + 1][0] = vv.z; bv[2 * jp + 1][1] = vv.w;
                }
                u32 a0[4], a1[4];
                ldAr(a0, XU, PX, 0,  k8 * 8, lane);
                ldAr(a1, XU, PX, 16, k8 * 8, lane);
#pragma unroll
                for (int j = 0; j < 6; j++) {
                    mma8(c[0][j], a0, bv[j]);
                    mma8(c[1][j], a1, bv[j]);
                }
            }
            // writeback (tf32 bits): cols 0-127 -> q, 128-255 -> k, 256-383 -> vT
#pragma unroll
            for (int m = 0; m < 2; m++)
#pragma unroll
                for (int j = 0; j < 6; j++) {
                    int col = nw + j * 8 + 2 * (lane & 3);
                    int row = (lane >> 2) + m * 16;
                    float* c4 = c[m][j];
                    if (col < 128) {
                        *(ull*)&s.q[row * PX + col]       = pack2t(c4[0], c4[1]);
                        *(ull*)&s.q[(row + 8) * PX + col] = pack2t(c4[2], c4[3]);
                    } else if (col < 256) {
                        int cc = col - 128;
                        *(ull*)&s.k[row * PX + cc]        = pack2t(c4[0], c4[1]);
                        *(ull*)&s.k[(row + 8) * PX + cc]  = pack2t(c4[2], c4[3]);
                    } else {
                        int cc = col - 256;
                        s.vT[cc * PT + row]           = tff(c4[0]);
                        s.vT[(cc + 1) * PT + row]     = tff(c4[1]);
                        s.vT[cc * PT + row + 8]       = tff(c4[2]);
                        s.vT[(cc + 1) * PT + row + 8] = tff(c4[3]);
                    }
                }
            __syncthreads();
        }

        // ---------- P projections (warps 0-6, repacked tables) + scores (warp 7) ----------
        {
            if (w < 7) {
                const u32* Tb[3];
#pragma unroll
                for (int u = 0; u < 3; u++) {
                    int tile = w * 3 + u;
                    int tt = tile / 7, n = tile % 7;
                    Tb[u] = tbR + (((st * 3 + tt) * 16) * 7 + n) * 64;   // + k8*7*64
                }
                float pc[3][2][4];
#pragma unroll
                for (int u = 0; u < 3; u++)
#pragma unroll
                    for (int m = 0; m < 2; m++)
#pragma unroll
                        for (int r = 0; r < 4; r++) pc[u][m][r] = 0.f;
#pragma unroll 2
                for (int k8 = 0; k8 < 16; k8++) {
                    u32 bv[3][2];
#pragma unroll
                    for (int u = 0; u < 3; u++) {
                        uint2 vv = *(const uint2*)&Tb[u][((k8 * 7) << 6) + lane * 2];
                        bv[u][0] = vv.x; bv[u][1] = vv.y;
                    }
                    u32 a0[4], a1[4];
                    ldAr(a0, s.k, PX, 0,  k8 * 8, lane);
                    ldAr(a1, s.k, PX, 16, k8 * 8, lane);
#pragma unroll
                    for (int u = 0; u < 3; u++) {
                        mma8(pc[u][0], a0, bv[u]);
                        mma8(pc[u][1], a1, bv[u]);
                    }
                }
#pragma unroll
                for (int u = 0; u < 3; u++) {
                    int tile = w * 3 + u;
                    int tt = tile / 7, nc = (tile % 7) * 8;
                    float* Pb = s.U1 + tt * K_ * 56;
#pragma unroll
                    for (int m = 0; m < 2; m++) {
                        int col = nc + 2 * (lane & 3);
                        int row = (lane >> 2) + m * 16;
                        *(ull*)&Pb[row * 56 + col]       = pack2(pc[u][m][0], pc[u][m][1]);
                        *(ull*)&Pb[(row + 8) * 56 + col] = pack2(pc[u][m][2], pc[u][m][3]);
                    }
                }
            } else {
                float scv[4][2][4];
#pragma unroll
                for (int n = 0; n < 4; n++)
#pragma unroll
                    for (int m = 0; m < 2; m++)
#pragma unroll
                        for (int r = 0; r < 4; r++) scv[n][m][r] = 0.f;
#pragma unroll 2
                for (int k8 = 0; k8 < 16; k8++) {
                    const int kc = k8 * 8;
                    u32 a0[4], a1[4];
                    ldAr(a0, s.q, PX, 0,  kc, lane);
                    ldAr(a1, s.q, PX, 16, kc, lane);
#pragma unroll
                    for (int n = 0; n < 4; n++) {
                        u32 bv[2];
                        ldBnr(bv, s.k, PX, n * 8, kc, lane);
                        mma8(scv[n][0], a0, bv);
                        mma8(scv[n][1], a1, bv);
                    }
                }
#pragma unroll
                for (int n = 0; n < 4; n++)
#pragma unroll
                    for (int m = 0; m < 2; m++) {
                        int col = n * 8 + 2 * (lane & 3);
                        int row = (lane >> 2) + m * 16;
                        *(ull*)&s.sa[row * PT + col]       = pack2(scv[n][m][0], scv[n][m][1]);
                        *(ull*)&s.sa[(row + 8) * PT + col] = pack2(scv[n][m][2], scv[n][m][3]);
                    }
            }
            __syncthreads();
        }

        // ---------- bias gather + softmax (warp w rows 4w..4w+3) ----------
        {
            const int i0 = w * 4;
            float cxj = s.cx[lane], cyj = s.cy[lane], czj = s.cz[lane];
#pragma unroll
            for (int r = 0; r < 4; r++) {
                int i = i0 + r;
                int ix, iy, iz;
                if (st == 0) {
                    float dx = s.cx[i] - cxj;
                    float dy = s.cy[i] - cyj;
                    float dz = s.cz[i] - czj;
                    ix = min(max((int)floorf((dx + 0.25f) / 0.01f), 0), L_ - 1);
                    iy = min(max((int)floorf((dy + 0.25f) / 0.01f), 0), L_ - 1);
                    iz = min(max((int)floorf((dz + 0.25f) / 0.01f), 0), L_ - 1);
                    s.idxp[i][lane] = ix | (iy << 8) | (iz << 16);
                } else {
                    int pk = s.idxp[i][lane];
                    ix = pk & 255; iy = (pk >> 8) & 255; iz = (pk >> 16) & 255;
                }
                float sc = (s.sa[i * PT + lane]
                            + P0[i * 56 + ix] + P1[i * 56 + iy] + P2[i * 56 + iz])
                           * 0.08838834764831843f;
                float mx = sc;
#pragma unroll
                for (int o = 16; o; o >>= 1) mx = fmaxf(mx, __shfl_xor_sync(0xffffffffu, mx, o));
                float e = __expf(sc - mx);
                float sum = e;
#pragma unroll
                for (int o = 16; o; o >>= 1) sum += __shfl_xor_sync(0xffffffffu, sum, o);
                s.sa[i * PT + lane] = tff(e * (1.0f / sum));   // tf32 bits for mma
            }
        }
        __syncthreads();

        // ---------- f = attn @ v : A=sa[32][36] B=vT(n-major) ----------
        {
            float fc[2][2][4];
#pragma unroll
            for (int m = 0; m < 2; m++)
#pragma unroll
                for (int j = 0; j < 2; j++)
#pragma unroll
                    for (int r = 0; r < 4; r++) fc[m][j][r] = 0.f;
#pragma unroll
            for (int k8 = 0; k8 < 4; k8++) {
                int kc = k8 * 8;
                u32 a0[4], a1[4];
                ldAr(a0, s.sa, PT, 0,  kc, lane);
                ldAr(a1, s.sa, PT, 16, kc, lane);
#pragma unroll
                for (int j = 0; j < 2; j++) {
                    u32 bv[2];
                    ldBnr(bv, s.vT, PT, w * 16 + j * 8, kc, lane);
                    mma8(fc[0][j], a0, bv);
                    mma8(fc[1][j], a1, bv);
                }
            }
            // FO -> U1 as tf32 bits (P dead after softmax); next-stage X
#pragma unroll
            for (int m = 0; m < 2; m++)
#pragma unroll
                for (int j = 0; j < 2; j++) {
                    int col = w * 16 + j * 8 + 2 * (lane & 3);
                    int row = (lane >> 2) + m * 16;
                    *(ull*)&XU[row * PX + col]       = pack2t(fc[m][j][0], fc[m][j][1]);
                    *(ull*)&XU[(row + 8) * PX + col] = pack2t(fc[m][j][2], fc[m][j][3]);
                }
        }
        __syncthreads();

        // ---------- trans block st+1 ----------
        trans_mma(XU, trR + (st + 1) * 16 * 8 * 128, ht, w, lane);
        __syncthreads();
    }

    // ---- dump trans accumulator (float) to s.q ----
#pragma unroll
    for (int m = 0; m < 2; m++)
#pragma unroll
        for (int j = 0; j < 2; j++) {
            int col = w * 16 + j * 8 + 2 * (lane & 3);
            int row = (lane >> 2) + m * 16;
            *(ull*)&s.q[row * PX + col]       = pack2(ht[m][j][0], ht[m][j][1]);
            *(ull*)&s.q[(row + 8) * PX + col] = pack2(ht[m][j][2], ht[m][j][3]);
        }
    __syncthreads();

    // ================= LayerNorm + ReLU =================
    {
        const int i0 = w * 4;
        float4 g4 = *(const float4*)(ln_g + c0);
        float4 b4 = *(const float4*)(ln_b + c0);
#pragma unroll
        for (int r = 0; r < 4; r++) {
            int i = i0 + r;
            float4 h = *(const float4*)&s.q[i * PX + c0];
            float s1 = h.x + h.y + h.z + h.w;
            float s2 = h.x * h.x + h.y * h.y + h.z * h.z + h.w * h.w;
#pragma unroll
            for (int o = 16; o; o >>= 1) {
                s1 += __shfl_xor_sync(0xffffffffu, s1, o);
                s2 += __shfl_xor_sync(0xffffffffu, s2, o);
            }
            float mu   = s1 * (1.0f / 128.0f);
            float var  = s2 * (1.0f / 128.0f) - mu * mu;
            float rstd = rsqrtf(var + 1e-5f);
            h.x = fmaxf((h.x - mu) * rstd * g4.x + b4.x, 0.0f);
            h.y = fmaxf((h.y - mu) * rstd * g4.y + b4.y, 0.0f);
            h.z = fmaxf((h.z - mu) * rstd * g4.z + b4.z, 0.0f);
            h.w = fmaxf((h.w - mu) * rstd * g4.w + b4.w, 0.0f);
            *(float4*)&s.q[i * PX + c0] = h;
        }
    }
    __syncthreads();

    // ================= max-pool + outputs =================
    if (tid < D_) {
        float m = s.q[tid];
#pragma unroll
        for (int i = 1; i < K_; i++) m = fmaxf(m, s.q[i * PX + tid]);
        s.pooled[tid] = m;
        int mm = g >> 6, nn = (g >> 3) & 7, tt = g & 7;
        int p = (tt << 6) + (nn << 3) + mm;          // transpose(0,3,2,1,4)
        out[((long long)b * G_ + p) * D_ + tid] = m;
    }
    __syncthreads();

#pragma unroll
    for (int rr = 0; rr < 4; rr++) {
        int e = tid + TPB * rr;
        int row = e >> 5, c4 = e & 31;
        float4 val = *(const float4*)&s.pooled[c4 * 4];
        *(float4*)(ret + ((long long)b * N_ + s.gidx[row]) * D_ + c4 * 4) = val;
    }
}

extern "C" void kernel_launch(void* const* d_in, const int* in_sizes, int n_in,
                              void* d_out, int out_size)
{
    const float* inputs      = (const float*)d_in[0];
    const float* coordinates = (const float*)d_in[1];
    const float* qkv_w       = (const float*)d_in[2];
    const float* qkv_b       = (const float*)d_in[3];
    const float* table_x     = (const float*)d_in[4];
    const float* table_y     = (const float*)d_in[5];
    const float* table_z     = (const float*)d_in[6];
    const float* trans_w     = (const float*)d_in[7];
    const float* trans_b     = (const float*)d_in[8];
    const float* ln_g        = (const float*)d_in[9];
    const float* ln_b        = (const float*)d_in[10];
    const int*   groups      = (const int*)d_in[11];

    float* out = (float*)d_out;                      // [B, 512, 128]
    float* ret = out + (size_t)B_ * G_ * D_;         // [B, 16384, 128]

    repack_kernel<<<(190464 + TPB - 1) / TPB, TPB>>>(
        qkv_w, trans_w, table_x, table_y, table_z);

    cudaFuncSetAttribute(voxel_encoder_kernel,
                         cudaFuncAttributeMaxDynamicSharedMemorySize,
                         (int)sizeof(Smem));

    voxel_encoder_kernel<<<B_ * G_, TPB, sizeof(Smem)>>>(
        inputs, coordinates, qkv_b, trans_b, ln_g, ln_b, groups, out, ret);
}

// round 6
// speedup vs baseline: 9.0837x; 1.6367x over previous
#include <cuda_runtime.h>
#include <cuda_fp16.h>

#define B_   2
#define G_   512
#define K_   32
#define D_   128
#define N_   16384
#define L_   50
#define S_   2
#define TPB  256
#define SX   136     // half stride for X / q / k rows
#define SV   40      // half stride for vT rows (d-major)
#define SA   40      // half stride for attn rows
#define SSC  36      // f32 stride for scores
#define SP   52      // f32 stride for P

typedef unsigned long long ull;
typedef unsigned int u32;

// fragment-order fp16 (half2-packed) weights, rebuilt by repack_kernel each launch
__device__ u32 qkvR[2 * 8 * 8 * 3 * 128];   // 49152 u32
__device__ u32 trR [3 * 8 * 8 * 128];       // 24576 u32
__device__ u32 tbR [2 * 3 * 8 * 7 * 64];    // 21504 u32

__device__ __forceinline__ u32 packh(float a, float b) {
    __half2 h = __floats2half2_rn(a, b);
    return *(u32*)&h;
}
__device__ __forceinline__ ull pack2(float x, float y) {
    ull r; asm("mov.b64 %0, {%1, %2};" : "=l"(r) : "f"(x), "f"(y)); return r;
}
__device__ __forceinline__ void mma16(float* c, const u32* a, const u32* b) {
    asm("mma.sync.aligned.m16n8k16.row.col.f32.f16.f16.f32 "
        "{%0,%1,%2,%3},{%4,%5,%6,%7},{%8,%9},{%0,%1,%2,%3};"
        : "+f"(c[0]), "+f"(c[1]), "+f"(c[2]), "+f"(c[3])
        : "r"(a[0]), "r"(a[1]), "r"(a[2]), "r"(a[3]), "r"(b[0]), "r"(b[1]));
}
// A fragment (16x16 f16) via ldmatrix.x4 from row-major half smem
__device__ __forceinline__ void ldsmA(u32* a, const __half* S, int strideH,
                                      int mr, int kc, int lane) {
    const __half* p = S + (mr + (lane & 15)) * strideH + kc + ((lane >> 4) << 3);
    u32 sa_ = (u32)__cvta_generic_to_shared((void*)p);
    asm volatile("ldmatrix.sync.aligned.m8n8.x4.shared.b16 {%0,%1,%2,%3}, [%4];"
                 : "=r"(a[0]), "=r"(a[1]), "=r"(a[2]), "=r"(a[3]) : "r"(sa_));
}
// B fragment from n-major half smem: B[k][n] at S[n*strideH + k] (k contiguous)
__device__ __forceinline__ void ldBh(u32* b, const __half* S, int strideH,
                                     int nc, int kc, int lane) {
    const u32* p = (const u32*)(S + (nc + (lane >> 2)) * strideH + kc) + (lane & 3);
    b[0] = p[0]; b[1] = p[4];
}

// ---------------- repack: f32 weights -> fragment-order half2 ----------------
__global__ void repack_kernel(const float* __restrict__ qkv_w,
                              const float* __restrict__ trans_w,
                              const float* __restrict__ tx,
                              const float* __restrict__ ty,
                              const float* __restrict__ tz)
{
    int e = blockIdx.x * TPB + threadIdx.x;
    if (e < 49152) {                                    // qkv
        int qq = e & 3, lane = (e >> 2) & 31;
        int f = e >> 7;
        int p   = f % 3;  f /= 3;
        int w   = f % 8;  f /= 8;
        int k16 = f % 8;
        int st  = f / 8;
        int tile = p * 2 + (qq >> 1), breg = qq & 1;
        int col  = w * 48 + tile * 8 + (lane >> 2);
        int krow = k16 * 16 + 2 * (lane & 3) + 8 * breg;
        const float* W = qkv_w + st * 49152;
        qkvR[e] = packh(W[krow * 384 + col], W[(krow + 1) * 384 + col]);
    } else if (e < 73728) {                             // trans
        int e2 = e - 49152;
        int qq = e2 & 3, lane = (e2 >> 2) & 31;
        int f = e2 >> 7;
        int w   = f % 8;  f /= 8;
        int k16 = f % 8;
        int blk = f / 8;
        int j = qq >> 1, breg = qq & 1;
        int col  = w * 16 + j * 8 + (lane >> 2);
        int krow = k16 * 16 + 2 * (lane & 3) + 8 * breg;
        const float* W = trans_w + blk * 16384;
        trR[e2] = packh(W[krow * 128 + col], W[(krow + 1) * 128 + col]);
    } else if (e < 95232) {                             // tables
        int e3 = e - 73728;
        int qq = e3 & 1, lane = (e3 >> 1) & 31;
        int f = e3 >> 6;
        int n   = f % 7;  f /= 7;
        int k16 = f % 8;  f /= 8;
        int t   = f % 3;
        int st  = f / 3;
        const float* T = (t == 0 ? tx : (t == 1 ? ty : tz)) + (st * 3 + 1) * L_ * D_;
        int nn = n * 8 + (lane >> 2);       // <=55, in-bounds of table alloc; never indexed >49
        int kk = k16 * 16 + 2 * (lane & 3) + 8 * qq;
        tbR[e3] = packh(T[nn * D_ + kk], T[nn * D_ + kk + 1]);
    }
}

// ---------------- shared memory (~60 KB -> 2 CTAs/SM) ----------------
struct __align__(16) Smem {
    float  Pf[3 * K_ * SP];  // P f32 [3][32][52]; first 8704B alias X/FO half[32][136]; H f32 at end
    __half q [K_ * SX];      // fp16
    __half k [K_ * SX];      // fp16
    __half vT[D_ * SV];      // v transposed [d][j], fp16
    float  sc[K_ * SSC];     // raw scores f32
    __half at[K_ * SA];      // attn fp16
    int    idxp[K_][K_];     // packed quant indices (stage 0 -> 1)
    float  cx[K_], cy[K_], cz[K_];
    float  pooled[D_];
    int    gidx[K_];
};

// ht += X @ W-block (repacked half2); warp w owns cols [16w,16w+16)
__device__ __forceinline__ void trans_mma(const __half* __restrict__ X,
                                          const u32* __restrict__ Rb,
                                          float ht[2][2][4], int w, int lane)
{
#pragma unroll
    for (int k16 = 0; k16 < 8; k16++) {
        uint4 vv = *(const uint4*)(Rb + ((k16 * 8 + w) << 7) + lane * 4);
        u32 b0[2] = {vv.x, vv.y}, b1[2] = {vv.z, vv.w};
        u32 a0[4], a1[4];
        ldsmA(a0, X, SX, 0,  k16 * 16, lane);
        ldsmA(a1, X, SX, 16, k16 * 16, lane);
        mma16(ht[0][0], a0, b0); mma16(ht[1][0], a1, b0);
        mma16(ht[0][1], a0, b1); mma16(ht[1][1], a1, b1);
    }
}

__global__ void __launch_bounds__(TPB, 2)
voxel_encoder_kernel(const float* __restrict__ inputs,
                     const float* __restrict__ coordinates,
                     const float* __restrict__ qkv_b,
                     const float* __restrict__ trans_b,
                     const float* __restrict__ ln_g,
                     const float* __restrict__ ln_b,
                     const int*   __restrict__ groups,
                     float* __restrict__ out,
                     float* __restrict__ ret)
{
    extern __shared__ __align__(16) char smem_raw[];
    Smem& s = *reinterpret_cast<Smem*>(smem_raw);

    const int tid  = threadIdx.x;
    const int w    = tid >> 5;
    const int lane = tid & 31;
    const int bg   = blockIdx.x;
    const int b    = bg / G_;
    const int g    = bg % G_;
    const int c0   = lane * 4;

    __half* XU = (__half*)s.Pf;               // X / FO overlay P region
    float*  P0 = s.Pf;
    float*  P1 = s.Pf + K_ * SP;
    float*  P2 = s.Pf + 2 * K_ * SP;

    // ---- gather indices + coordinates ----
    if (tid < K_) {
        int p = groups[bg * K_ + tid];
        s.gidx[tid] = p;
        const float* c = coordinates + ((long long)b * N_ + p) * 3;
        s.cx[tid] = c[0]; s.cy[tid] = c[1]; s.cz[tid] = c[2];
    }
    __syncthreads();

    // ---- gather features -> XU as fp16 ----
#pragma unroll
    for (int rr = 0; rr < 4; rr++) {
        int e = tid + TPB * rr;
        int row = e >> 5, c4 = e & 31;
        float4 val = *(const float4*)(inputs + ((long long)b * N_ + s.gidx[row]) * D_ + c4 * 4);
        uint2 hv; hv.x = packh(val.x, val.y); hv.y = packh(val.z, val.w);
        *(uint2*)(XU + row * SX + c4 * 4) = hv;
    }
    __syncthreads();

    // ---- trans accumulator in registers: warp w cols [16w,16w+16) ----
    float ht[2][2][4];
#pragma unroll
    for (int j = 0; j < 2; j++) {
        int col = w * 16 + j * 8 + 2 * (lane & 3);
        float b0 = trans_b[col], b1 = trans_b[col + 1];
        ht[0][j][0] = b0; ht[0][j][1] = b1; ht[0][j][2] = b0; ht[0][j][3] = b1;
        ht[1][j][0] = b0; ht[1][j][1] = b1; ht[1][j][2] = b0; ht[1][j][3] = b1;
    }

    trans_mma(XU, trR, ht, w, lane);     // block 0 on raw features

    // ================= attention stages =================
    for (int st = 0; st < S_; st++) {
        // ---------- qkv: C[32][384] = X @ Wq + b; warp w cols [48w,48w+48) ----------
        {
            const float* bb = qkv_b + st * 3 * D_;
            const int nw = w * 48;
            float c[2][6][4];
#pragma unroll
            for (int j = 0; j < 6; j++) {
                float b0 = bb[nw + j * 8 + 2 * (lane & 3)];
                float b1 = bb[nw + j * 8 + 2 * (lane & 3) + 1];
                c[0][j][0] = b0; c[0][j][1] = b1; c[0][j][2] = b0; c[0][j][3] = b1;
                c[1][j][0] = b0; c[1][j][1] = b1; c[1][j][2] = b0; c[1][j][3] = b1;
            }
#pragma unroll
            for (int k16 = 0; k16 < 8; k16++) {
                const u32* rp = qkvR + (((st * 8 + k16) * 8 + w) * 3) * 128 + lane * 4;
                uint4 v0 = *(const uint4*)(rp);
                uint4 v1 = *(const uint4*)(rp + 128);
                uint4 v2 = *(const uint4*)(rp + 256);
                u32 bv[6][2] = {{v0.x, v0.y}, {v0.z, v0.w}, {v1.x, v1.y},
                                {v1.z, v1.w}, {v2.x, v2.y}, {v2.z, v2.w}};
                u32 a0[4], a1[4];
                ldsmA(a0, XU, SX, 0,  k16 * 16, lane);
                ldsmA(a1, XU, SX, 16, k16 * 16, lane);
#pragma unroll
                for (int j = 0; j < 6; j++) {
                    mma16(c[0][j], a0, bv[j]);
                    mma16(c[1][j], a1, bv[j]);
                }
            }
            // writeback fp16: cols 0-127 -> q, 128-255 -> k, 256-383 -> vT (transposed)
#pragma unroll
            for (int m = 0; m < 2; m++)
#pragma unroll
                for (int j = 0; j < 6; j++) {
                    int col = nw + j * 8 + 2 * (lane & 3);
                    int row = (lane >> 2) + m * 16;
                    float* c4 = c[m][j];
                    if (col < 128) {
                        *(u32*)(s.q + row * SX + col)       = packh(c4[0], c4[1]);
                        *(u32*)(s.q + (row + 8) * SX + col) = packh(c4[2], c4[3]);
                    } else if (col < 256) {
                        int cc = col - 128;
                        *(u32*)(s.k + row * SX + cc)        = packh(c4[0], c4[1]);
                        *(u32*)(s.k + (row + 8) * SX + cc)  = packh(c4[2], c4[3]);
                    } else {
                        int cc = col - 256;
                        s.vT[cc * SV + row]           = __float2half_rn(c4[0]);
                        s.vT[(cc + 1) * SV + row]     = __float2half_rn(c4[1]);
                        s.vT[cc * SV + row + 8]       = __float2half_rn(c4[2]);
                        s.vT[(cc + 1) * SV + row + 8] = __float2half_rn(c4[3]);
                    }
                }
            __syncthreads();
        }

        // ---------- P projections (warps 0-6) + scores (warp 7) ----------
        {
            if (w < 7) {
                float pc[3][2][4];
#pragma unroll
                for (int u = 0; u < 3; u++)
#pragma unroll
                    for (int m = 0; m < 2; m++)
#pragma unroll
                        for (int r = 0; r < 4; r++) pc[u][m][r] = 0.f;
#pragma unroll
                for (int k16 = 0; k16 < 8; k16++) {
                    u32 bv[3][2];
#pragma unroll
                    for (int u = 0; u < 3; u++) {
                        int tile = w * 3 + u;
                        int tt = tile / 7, n = tile % 7;
                        uint2 vv = *(const uint2*)(tbR +
                            ((((st * 3 + tt) * 8 + k16) * 7 + n) << 6) + lane * 2);
                        bv[u][0] = vv.x; bv[u][1] = vv.y;
                    }
                    u32 a0[4], a1[4];
                    ldsmA(a0, s.k, SX, 0,  k16 * 16, lane);
                    ldsmA(a1, s.k, SX, 16, k16 * 16, lane);
#pragma unroll
                    for (int u = 0; u < 3; u++) {
                        mma16(pc[u][0], a0, bv[u]);
                        mma16(pc[u][1], a1, bv[u]);
                    }
                }
#pragma unroll
                for (int u = 0; u < 3; u++) {
                    int tile = w * 3 + u;
                    int tt = tile / 7, nc = (tile % 7) * 8;
                    float* Pb = s.Pf + tt * K_ * SP;
                    int col = nc + 2 * (lane & 3);
                    bool ok = (col < SP - 1);        // clip tile 6 cols 52-55 (never read)
#pragma unroll
                    for (int m = 0; m < 2; m++) {
                        int row = (lane >> 2) + m * 16;
                        if (ok) {
                            *(ull*)&Pb[row * SP + col]       = pack2(pc[u][m][0], pc[u][m][1]);
                            *(ull*)&Pb[(row + 8) * SP + col] = pack2(pc[u][m][2], pc[u][m][3]);
                        }
                    }
                }
            } else {
                float scv[4][2][4];
#pragma unroll
                for (int n = 0; n < 4; n++)
#pragma unroll
                    for (int m = 0; m < 2; m++)
#pragma unroll
                        for (int r = 0; r < 4; r++) scv[n][m][r] = 0.f;
#pragma unroll
                for (int k16 = 0; k16 < 8; k16++) {
                    u32 a0[4], a1[4];
                    ldsmA(a0, s.q, SX, 0,  k16 * 16, lane);
                    ldsmA(a1, s.q, SX, 16, k16 * 16, lane);
#pragma unroll
                    for (int n = 0; n < 4; n++) {
                        u32 bv[2];
                        ldBh(bv, s.k, SX, n * 8, k16 * 16, lane);
                        mma16(scv[n][0], a0, bv);
                        mma16(scv[n][1], a1, bv);
                    }
                }
#pragma unroll
                for (int n = 0; n < 4; n++)
#pragma unroll
                    for (int m = 0; m < 2; m++) {
                        int col = n * 8 + 2 * (lane & 3);
                        int row = (lane >> 2) + m * 16;
                        *(ull*)&s.sc[row * SSC + col]       = pack2(scv[n][m][0], scv[n][m][1]);
                        *(ull*)&s.sc[(row + 8) * SSC + col] = pack2(scv[n][m][2], scv[n][m][3]);
                    }
            }
            __syncthreads();
        }

        // ---------- bias gather + softmax (warp w rows 4w..4w+3) ----------
        {
            const int i0 = w * 4;
            float cxj = s.cx[lane], cyj = s.cy[lane], czj = s.cz[lane];
#pragma unroll
            for (int r = 0; r < 4; r++) {
                int i = i0 + r;
                int ix, iy, iz;
                if (st == 0) {
                    float dx = s.cx[i] - cxj;
                    float dy = s.cy[i] - cyj;
                    float dz = s.cz[i] - czj;
                    ix = min(max((int)floorf((dx + 0.25f) / 0.01f), 0), L_ - 1);
                    iy = min(max((int)floorf((dy + 0.25f) / 0.01f), 0), L_ - 1);
                    iz = min(max((int)floorf((dz + 0.25f) / 0.01f), 0), L_ - 1);
                    s.idxp[i][lane] = ix | (iy << 8) | (iz << 16);
                } else {
                    int pk = s.idxp[i][lane];
                    ix = pk & 255; iy = (pk >> 8) & 255; iz = (pk >> 16) & 255;
                }
                float scr = (s.sc[i * SSC + lane]
                             + P0[i * SP + ix] + P1[i * SP + iy] + P2[i * SP + iz])
                            * 0.08838834764831843f;   // 1/sqrt(128)
                float mx = scr;
#pragma unroll
                for (int o = 16; o; o >>= 1) mx = fmaxf(mx, __shfl_xor_sync(0xffffffffu, mx, o));
                float e = __expf(scr - mx);
                float sum = e;
#pragma unroll
                for (int o = 16; o; o >>= 1) sum += __shfl_xor_sync(0xffffffffu, sum, o);
                s.at[i * SA + lane] = __float2half_rn(e * (1.0f / sum));
            }
        }
        __syncthreads();

        // ---------- f = attn @ v : A=at[32][32] B=vT (d-major, k=j contiguous) ----------
        {
            float fc[2][2][4];
#pragma unroll
            for (int m = 0; m < 2; m++)
#pragma unroll
                for (int j = 0; j < 2; j++)
#pragma unroll
                    for (int r = 0; r < 4; r++) fc[m][j][r] = 0.f;
#pragma unroll
            for (int k16 = 0; k16 < 2; k16++) {
                int kc = k16 * 16;
                u32 a0[4], a1[4];
                ldsmA(a0, s.at, SA, 0,  kc, lane);
                ldsmA(a1, s.at, SA, 16, kc, lane);
#pragma unroll
                for (int j = 0; j < 2; j++) {
                    u32 bv[2];
                    ldBh(bv, s.vT, SV, w * 16 + j * 8, kc, lane);
                    mma16(fc[0][j], a0, bv);
                    mma16(fc[1][j], a1, bv);
                }
            }
            // FO -> XU as fp16 (P dead after softmax); next-stage X
#pragma unroll
            for (int m = 0; m < 2; m++)
#pragma unroll
                for (int j = 0; j < 2; j++) {
                    int col = w * 16 + j * 8 + 2 * (lane & 3);
                    int row = (lane >> 2) + m * 16;
                    *(u32*)(XU + row * SX + col)       = packh(fc[m][j][0], fc[m][j][1]);
                    *(u32*)(XU + (row + 8) * SX + col) = packh(fc[m][j][2], fc[m][j][3]);
                }
        }
        __syncthreads();

        // ---------- trans block st+1 ----------
        trans_mma(XU, trR + (st + 1) * 8 * 8 * 128, ht, w, lane);
        __syncthreads();
    }

    // ---- dump trans accumulator f32 -> H (reuse P region; X dead) ----
    float* H = s.Pf;
#pragma unroll
    for (int m = 0; m < 2; m++)
#pragma unroll
        for (int j = 0; j < 2; j++) {
            int col = w * 16 + j * 8 + 2 * (lane & 3);
            int row = (lane >> 2) + m * 16;
            *(ull*)&H[row * 128 + col]       = pack2(ht[m][j][0], ht[m][j][1]);
            *(ull*)&H[(row + 8) * 128 + col] = pack2(ht[m][j][2], ht[m][j][3]);
        }
    __syncthreads();

    // ================= LayerNorm + ReLU =================
    {
        const int i0 = w * 4;
        float4 g4 = *(const float4*)(ln_g + c0);
        float4 b4 = *(const float4*)(ln_b + c0);
#pragma unroll
        for (int r = 0; r < 4; r++) {
            int i = i0 + r;
            float4 h = *(const float4*)&H[i * 128 + c0];
            float s1 = h.x + h.y + h.z + h.w;
            float s2 = h.x * h.x + h.y * h.y + h.z * h.z + h.w * h.w;
#pragma unroll
            for (int o = 16; o; o >>= 1) {
                s1 += __shfl_xor_sync(0xffffffffu, s1, o);
                s2 += __shfl_xor_sync(0xffffffffu, s2, o);
            }
            float mu   = s1 * (1.0f / 128.0f);
            float var  = s2 * (1.0f / 128.0f) - mu * mu;
            float rstd = rsqrtf(var + 1e-5f);
            h.x = fmaxf((h.x - mu) * rstd * g4.x + b4.x, 0.0f);
            h.y = fmaxf((h.y - mu) * rstd * g4.y + b4.y, 0.0f);
            h.z = fmaxf((h.z - mu) * rstd * g4.z + b4.z, 0.0f);
            h.w = fmaxf((h.w - mu) * rstd * g4.w + b4.w, 0.0f);
            *(float4*)&H[i * 128 + c0] = h;
        }
    }
    __syncthreads();

    // ================= max-pool + outputs =================
    if (tid < D_) {
        float m = H[tid];
#pragma unroll
        for (int i = 1; i < K_; i++) m = fmaxf(m, H[i * 128 + tid]);
        s.pooled[tid] = m;
        int mm = g >> 6, nn = (g >> 3) & 7, tt = g & 7;
        int p = (tt << 6) + (nn << 3) + mm;          // transpose(0,3,2,1,4)
        out[((long long)b * G_ + p) * D_ + tid] = m;
    }
    __syncthreads();

#pragma unroll
    for (int rr = 0; rr < 4; rr++) {
        int e = tid + TPB * rr;
        int row = e >> 5, c4 = e & 31;
        float4 val = *(const float4*)&s.pooled[c4 * 4];
        *(float4*)(ret + ((long long)b * N_ + s.gidx[row]) * D_ + c4 * 4) = val;
    }
}

extern "C" void kernel_launch(void* const* d_in, const int* in_sizes, int n_in,
                              void* d_out, int out_size)
{
    const float* inputs      = (const float*)d_in[0];
    const float* coordinates = (const float*)d_in[1];
    const float* qkv_w       = (const float*)d_in[2];
    const float* qkv_b       = (const float*)d_in[3];
    const float* table_x     = (const float*)d_in[4];
    const float* table_y     = (const float*)d_in[5];
    const float* table_z     = (const float*)d_in[6];
    const float* trans_w     = (const float*)d_in[7];
    const float* trans_b     = (const float*)d_in[8];
    const float* ln_g        = (const float*)d_in[9];
    const float* ln_b        = (const float*)d_in[10];
    const int*   groups      = (const int*)d_in[11];

    float* out = (float*)d_out;                      // [B, 512, 128]
    float* ret = out + (size_t)B_ * G_ * D_;         // [B, 16384, 128]

    repack_kernel<<<(95232 + TPB - 1) / TPB, TPB>>>(
        qkv_w, trans_w, table_x, table_y, table_z);

    cudaFuncSetAttribute(voxel_encoder_kernel,
                         cudaFuncAttributeMaxDynamicSharedMemorySize,
                         (int)sizeof(Smem));

    voxel_encoder_kernel<<<B_ * G_, TPB, sizeof(Smem)>>>(
        inputs, coordinates, qkv_b, trans_b, ln_g, ln_b, groups, out, ret);
}

// round 7
// speedup vs baseline: 9.1670x; 1.0092x over previous
#include <cuda_runtime.h>
#include <cuda_fp16.h>

#define B_   2
#define G_   512
#define K_   32
#define D_   128
#define N_   16384
#define L_   50
#define S_   2
#define TPB  256
#define SX   136     // half stride for X / q / k rows
#define SV   40      // half stride for vT rows (d-major)
#define SA   40      // half stride for attn rows
#define SSC  36      // f32 stride for scores
#define SP   52      // f32 stride for P

typedef unsigned long long ull;
typedef unsigned int u32;

// fragment-order fp16 (half2-packed) weights, rebuilt by repack_kernel each launch
__device__ u32 qkvR[2 * 8 * 8 * 3 * 128];   // 49152 u32
__device__ u32 trR [3 * 8 * 8 * 128];       // 24576 u32
__device__ u32 tbR [2 * 3 * 8 * 7 * 64];    // 21504 u32

__device__ __forceinline__ u32 packh(float a, float b) {
    __half2 h = __floats2half2_rn(a, b);
    return *(u32*)&h;
}
__device__ __forceinline__ ull pack2(float x, float y) {
    ull r; asm("mov.b64 %0, {%1, %2};" : "=l"(r) : "f"(x), "f"(y)); return r;
}
__device__ __forceinline__ void mma16(float* c, const u32* a, const u32* b) {
    asm("mma.sync.aligned.m16n8k16.row.col.f32.f16.f16.f32 "
        "{%0,%1,%2,%3},{%4,%5,%6,%7},{%8,%9},{%0,%1,%2,%3};"
        : "+f"(c[0]), "+f"(c[1]), "+f"(c[2]), "+f"(c[3])
        : "r"(a[0]), "r"(a[1]), "r"(a[2]), "r"(a[3]), "r"(b[0]), "r"(b[1]));
}
// A fragment (16x16 f16) via ldmatrix.x4 from row-major half smem
__device__ __forceinline__ void ldsmA(u32* a, const __half* S, int strideH,
                                      int mr, int kc, int lane) {
    const __half* p = S + (mr + (lane & 15)) * strideH + kc + ((lane >> 4) << 3);
    u32 sa_ = (u32)__cvta_generic_to_shared((void*)p);
    asm volatile("ldmatrix.sync.aligned.m8n8.x4.shared.b16 {%0,%1,%2,%3}, [%4];"
                 : "=r"(a[0]), "=r"(a[1]), "=r"(a[2]), "=r"(a[3]) : "r"(sa_));
}
// B fragment from n-major half smem: B[k][n] at S[n*strideH + k] (k contiguous)
__device__ __forceinline__ void ldBh(u32* b, const __half* S, int strideH,
                                     int nc, int kc, int lane) {
    const u32* p = (const u32*)(S + (nc + (lane >> 2)) * strideH + kc) + (lane & 3);
    b[0] = p[0]; b[1] = p[4];
}

// ---------------- repack: f32 weights -> fragment-order half2 ----------------
__global__ void repack_kernel(const float* __restrict__ qkv_w,
                              const float* __restrict__ trans_w,
                              const float* __restrict__ tx,
                              const float* __restrict__ ty,
                              const float* __restrict__ tz)
{
    int e = blockIdx.x * TPB + threadIdx.x;
    if (e < 49152) {                                    // qkv
        int qq = e & 3, lane = (e >> 2) & 31;
        int f = e >> 7;
        int p   = f % 3;  f /= 3;
        int w   = f % 8;  f /= 8;
        int k16 = f % 8;
        int st  = f / 8;
        int tile = p * 2 + (qq >> 1), breg = qq & 1;
        int col  = w * 48 + tile * 8 + (lane >> 2);
        int krow = k16 * 16 + 2 * (lane & 3) + 8 * breg;
        const float* W = qkv_w + st * 49152;
        qkvR[e] = packh(W[krow * 384 + col], W[(krow + 1) * 384 + col]);
    } else if (e < 73728) {                             // trans
        int e2 = e - 49152;
        int qq = e2 & 3, lane = (e2 >> 2) & 31;
        int f = e2 >> 7;
        int w   = f % 8;  f /= 8;
        int k16 = f % 8;
        int blk = f / 8;
        int j = qq >> 1, breg = qq & 1;
        int col  = w * 16 + j * 8 + (lane >> 2);
        int krow = k16 * 16 + 2 * (lane & 3) + 8 * breg;
        const float* W = trans_w + blk * 16384;
        trR[e2] = packh(W[krow * 128 + col], W[(krow + 1) * 128 + col]);
    } else if (e < 95232) {                             // tables
        int e3 = e - 73728;
        int qq = e3 & 1, lane = (e3 >> 1) & 31;
        int f = e3 >> 6;
        int n   = f % 7;  f /= 7;
        int k16 = f % 8;  f /= 8;
        int t   = f % 3;
        int st  = f / 3;
        const float* T = (t == 0 ? tx : (t == 1 ? ty : tz)) + (st * 3 + 1) * L_ * D_;
        int nn = n * 8 + (lane >> 2);       // <=55, in-bounds of table alloc; never indexed >49
        int kk = k16 * 16 + 2 * (lane & 3) + 8 * qq;
        tbR[e3] = packh(T[nn * D_ + kk], T[nn * D_ + kk + 1]);
    }
}

// ---------------- shared memory (~56 KB -> 3 CTAs/SM) ----------------
struct __align__(16) Smem {
    float  Pf[3 * K_ * SP];  // P f32 [3][32][52]; first 8704B alias X/FO half[32][136]; H at end
    __half q [K_ * SX];      // fp16
    __half k [K_ * SX];      // fp16
    __half vT[D_ * SV];      // v transposed [d][j], fp16
    float  sc[K_ * SSC];     // raw scores f32
    __half at[K_ * SA];      // attn fp16
    float  cx[K_], cy[K_], cz[K_];
    float  pooled[D_];
    int    gidx[K_];
};

// ht += X @ W-block (repacked half2); warp w owns cols [16w,16w+16)
__device__ __forceinline__ void trans_mma(const __half* __restrict__ X,
                                          const u32* __restrict__ Rb,
                                          float ht[2][2][4], int w, int lane)
{
#pragma unroll
    for (int k16 = 0; k16 < 8; k16++) {
        uint4 vv = *(const uint4*)(Rb + ((k16 * 8 + w) << 7) + lane * 4);
        u32 b0[2] = {vv.x, vv.y}, b1[2] = {vv.z, vv.w};
        u32 a0[4], a1[4];
        ldsmA(a0, X, SX, 0,  k16 * 16, lane);
        ldsmA(a1, X, SX, 16, k16 * 16, lane);
        mma16(ht[0][0], a0, b0); mma16(ht[1][0], a1, b0);
        mma16(ht[0][1], a0, b1); mma16(ht[1][1], a1, b1);
    }
}

// one qkv column pass: j-tiles [J0, J0+JN) of warp w's 6; low register pressure
template<int J0, int JN>
__device__ __forceinline__ void qkv_pass(Smem& s, const __half* __restrict__ XU,
                                         const float* __restrict__ bb,
                                         int st, int w, int lane)
{
    const int nw = w * 48;
    float c[2][JN][4];
#pragma unroll
    for (int j = 0; j < JN; j++) {
        float b0 = bb[nw + (J0 + j) * 8 + 2 * (lane & 3)];
        float b1 = bb[nw + (J0 + j) * 8 + 2 * (lane & 3) + 1];
        c[0][j][0] = b0; c[0][j][1] = b1; c[0][j][2] = b0; c[0][j][3] = b1;
        c[1][j][0] = b0; c[1][j][1] = b1; c[1][j][2] = b0; c[1][j][3] = b1;
    }
#pragma unroll
    for (int k16 = 0; k16 < 8; k16++) {
        const u32* rp = qkvR + (((st * 8 + k16) * 8 + w) * 3) * 128 + lane * 4;
        u32 bv[JN][2];
#pragma unroll
        for (int jj = 0; jj < JN / 2; jj++) {
            uint4 v = *(const uint4*)(rp + ((J0 / 2) + jj) * 128);
            bv[2 * jj][0] = v.x;     bv[2 * jj][1] = v.y;
            bv[2 * jj + 1][0] = v.z; bv[2 * jj + 1][1] = v.w;
        }
        u32 a0[4], a1[4];
        ldsmA(a0, XU, SX, 0,  k16 * 16, lane);
        ldsmA(a1, XU, SX, 16, k16 * 16, lane);
#pragma unroll
        for (int j = 0; j < JN; j++) {
            mma16(c[0][j], a0, bv[j]);
            mma16(c[1][j], a1, bv[j]);
        }
    }
    // writeback fp16: cols 0-127 -> q, 128-255 -> k, 256-383 -> vT (transposed)
#pragma unroll
    for (int m = 0; m < 2; m++)
#pragma unroll
        for (int j = 0; j < JN; j++) {
            int col = nw + (J0 + j) * 8 + 2 * (lane & 3);
            int row = (lane >> 2) + m * 16;
            float* c4 = c[m][j];
            if (col < 128) {
                *(u32*)(s.q + row * SX + col)       = packh(c4[0], c4[1]);
                *(u32*)(s.q + (row + 8) * SX + col) = packh(c4[2], c4[3]);
            } else if (col < 256) {
                int cc = col - 128;
                *(u32*)(s.k + row * SX + cc)        = packh(c4[0], c4[1]);
                *(u32*)(s.k + (row + 8) * SX + cc)  = packh(c4[2], c4[3]);
            } else {
                int cc = col - 256;
                s.vT[cc * SV + row]           = __float2half_rn(c4[0]);
                s.vT[(cc + 1) * SV + row]     = __float2half_rn(c4[1]);
                s.vT[cc * SV + row + 8]       = __float2half_rn(c4[2]);
                s.vT[(cc + 1) * SV + row + 8] = __float2half_rn(c4[3]);
            }
        }
}

__global__ void __launch_bounds__(TPB, 3)
voxel_encoder_kernel(const float* __restrict__ inputs,
                     const float* __restrict__ coordinates,
                     const float* __restrict__ qkv_b,
                     const float* __restrict__ trans_b,
                     const float* __restrict__ ln_g,
                     const float* __restrict__ ln_b,
                     const int*   __restrict__ groups,
                     float* __restrict__ out,
                     float* __restrict__ ret)
{
    extern __shared__ __align__(16) char smem_raw[];
    Smem& s = *reinterpret_cast<Smem*>(smem_raw);

    const int tid  = threadIdx.x;
    const int w    = tid >> 5;
    const int lane = tid & 31;
    const int bg   = blockIdx.x;
    const int b    = bg / G_;
    const int g    = bg % G_;
    const int c0   = lane * 4;

    __half* XU = (__half*)s.Pf;               // X / FO overlay P region
    float*  P0 = s.Pf;
    float*  P1 = s.Pf + K_ * SP;
    float*  P2 = s.Pf + 2 * K_ * SP;

    // ---- gather indices + coordinates ----
    if (tid < K_) {
        int p = groups[bg * K_ + tid];
        s.gidx[tid] = p;
        const float* c = coordinates + ((long long)b * N_ + p) * 3;
        s.cx[tid] = c[0]; s.cy[tid] = c[1]; s.cz[tid] = c[2];
    }
    __syncthreads();

    // ---- gather features -> XU as fp16 ----
#pragma unroll
    for (int rr = 0; rr < 4; rr++) {
        int e = tid + TPB * rr;
        int row = e >> 5, c4 = e & 31;
        float4 val = *(const float4*)(inputs + ((long long)b * N_ + s.gidx[row]) * D_ + c4 * 4);
        uint2 hv; hv.x = packh(val.x, val.y); hv.y = packh(val.z, val.w);
        *(uint2*)(XU + row * SX + c4 * 4) = hv;
    }
    __syncthreads();

    // ---- trans accumulator in registers: warp w cols [16w,16w+16) ----
    float ht[2][2][4];
#pragma unroll
    for (int j = 0; j < 2; j++) {
        int col = w * 16 + j * 8 + 2 * (lane & 3);
        float b0 = trans_b[col], b1 = trans_b[col + 1];
        ht[0][j][0] = b0; ht[0][j][1] = b1; ht[0][j][2] = b0; ht[0][j][3] = b1;
        ht[1][j][0] = b0; ht[1][j][1] = b1; ht[1][j][2] = b0; ht[1][j][3] = b1;
    }

    trans_mma(XU, trR, ht, w, lane);     // block 0 on raw features

    // ================= attention stages =================
    for (int st = 0; st < S_; st++) {
        // ---------- qkv: two column passes (register relief for occ 3) ----------
        {
            const float* bb = qkv_b + st * 3 * D_;
            qkv_pass<0, 4>(s, XU, bb, st, w, lane);
            qkv_pass<4, 2>(s, XU, bb, st, w, lane);
            __syncthreads();
        }

        // ---------- P projections (warps 0-6) + scores (warp 7) ----------
        {
            if (w < 7) {
                float pc[3][2][4];
#pragma unroll
                for (int u = 0; u < 3; u++)
#pragma unroll
                    for (int m = 0; m < 2; m++)
#pragma unroll
                        for (int r = 0; r < 4; r++) pc[u][m][r] = 0.f;
#pragma unroll
                for (int k16 = 0; k16 < 8; k16++) {
                    u32 bv[3][2];
#pragma unroll
                    for (int u = 0; u < 3; u++) {
                        int tile = w * 3 + u;
                        int tt = tile / 7, n = tile % 7;
                        uint2 vv = *(const uint2*)(tbR +
                            ((((st * 3 + tt) * 8 + k16) * 7 + n) << 6) + lane * 2);
                        bv[u][0] = vv.x; bv[u][1] = vv.y;
                    }
                    u32 a0[4], a1[4];
                    ldsmA(a0, s.k, SX, 0,  k16 * 16, lane);
                    ldsmA(a1, s.k, SX, 16, k16 * 16, lane);
#pragma unroll
                    for (int u = 0; u < 3; u++) {
                        mma16(pc[u][0], a0, bv[u]);
                        mma16(pc[u][1], a1, bv[u]);
                    }
                }
#pragma unroll
                for (int u = 0; u < 3; u++) {
                    int tile = w * 3 + u;
                    int tt = tile / 7, nc = (tile % 7) * 8;
                    float* Pb = s.Pf + tt * K_ * SP;
                    int col = nc + 2 * (lane & 3);
                    bool ok = (col < SP - 1);        // clip tile 6 cols 52-55 (never read)
#pragma unroll
                    for (int m = 0; m < 2; m++) {
                        int row = (lane >> 2) + m * 16;
                        if (ok) {
                            *(ull*)&Pb[row * SP + col]       = pack2(pc[u][m][0], pc[u][m][1]);
                            *(ull*)&Pb[(row + 8) * SP + col] = pack2(pc[u][m][2], pc[u][m][3]);
                        }
                    }
                }
            } else {
                float scv[4][2][4];
#pragma unroll
                for (int n = 0; n < 4; n++)
#pragma unroll
                    for (int m = 0; m < 2; m++)
#pragma unroll
                        for (int r = 0; r < 4; r++) scv[n][m][r] = 0.f;
#pragma unroll
                for (int k16 = 0; k16 < 8; k16++) {
                    u32 a0[4], a1[4];
                    ldsmA(a0, s.q, SX, 0,  k16 * 16, lane);
                    ldsmA(a1, s.q, SX, 16, k16 * 16, lane);
#pragma unroll
                    for (int n = 0; n < 4; n++) {
                        u32 bv[2];
                        ldBh(bv, s.k, SX, n * 8, k16 * 16, lane);
                        mma16(scv[n][0], a0, bv);
                        mma16(scv[n][1], a1, bv);
                    }
                }
#pragma unroll
                for (int n = 0; n < 4; n++)
#pragma unroll
                    for (int m = 0; m < 2; m++) {
                        int col = n * 8 + 2 * (lane & 3);
                        int row = (lane >> 2) + m * 16;
                        *(ull*)&s.sc[row * SSC + col]       = pack2(scv[n][m][0], scv[n][m][1]);
                        *(ull*)&s.sc[(row + 8) * SSC + col] = pack2(scv[n][m][2], scv[n][m][3]);
                    }
            }
            __syncthreads();
        }

        // ---------- bias gather + softmax (warp w rows 4w..4w+3) ----------
        {
            const int i0 = w * 4;
            float cxj = s.cx[lane], cyj = s.cy[lane], czj = s.cz[lane];
#pragma unroll
            for (int r = 0; r < 4; r++) {
                int i = i0 + r;
                float dx = s.cx[i] - cxj;
                float dy = s.cy[i] - cyj;
                float dz = s.cz[i] - czj;
                int ix = min(max((int)floorf((dx + 0.25f) / 0.01f), 0), L_ - 1);
                int iy = min(max((int)floorf((dy + 0.25f) / 0.01f), 0), L_ - 1);
                int iz = min(max((int)floorf((dz + 0.25f) / 0.01f), 0), L_ - 1);
                float scr = (s.sc[i * SSC + lane]
                             + P0[i * SP + ix] + P1[i * SP + iy] + P2[i * SP + iz])
                            * 0.08838834764831843f;   // 1/sqrt(128)
                float mx = scr;
#pragma unroll
                for (int o = 16; o; o >>= 1) mx = fmaxf(mx, __shfl_xor_sync(0xffffffffu, mx, o));
                float e = __expf(scr - mx);
                float sum = e;
#pragma unroll
                for (int o = 16; o; o >>= 1) sum += __shfl_xor_sync(0xffffffffu, sum, o);
                s.at[i * SA + lane] = __float2half_rn(e * (1.0f / sum));
            }
        }
        __syncthreads();

        // ---------- f = attn @ v : A=at[32][32] B=vT (d-major, k=j contiguous) ----------
        {
            float fc[2][2][4];
#pragma unroll
            for (int m = 0; m < 2; m++)
#pragma unroll
                for (int j = 0; j < 2; j++)
#pragma unroll
                    for (int r = 0; r < 4; r++) fc[m][j][r] = 0.f;
#pragma unroll
            for (int k16 = 0; k16 < 2; k16++) {
                int kc = k16 * 16;
                u32 a0[4], a1[4];
                ldsmA(a0, s.at, SA, 0,  kc, lane);
                ldsmA(a1, s.at, SA, 16, kc, lane);
#pragma unroll
                for (int j = 0; j < 2; j++) {
                    u32 bv[2];
                    ldBh(bv, s.vT, SV, w * 16 + j * 8, kc, lane);
                    mma16(fc[0][j], a0, bv);
                    mma16(fc[1][j], a1, bv);
                }
            }
            // FO -> XU as fp16 (P dead after softmax); next-stage X
#pragma unroll
            for (int m = 0; m < 2; m++)
#pragma unroll
                for (int j = 0; j < 2; j++) {
                    int col = w * 16 + j * 8 + 2 * (lane & 3);
                    int row = (lane >> 2) + m * 16;
                    *(u32*)(XU + row * SX + col)       = packh(fc[m][j][0], fc[m][j][1]);
                    *(u32*)(XU + (row + 8) * SX + col) = packh(fc[m][j][2], fc[m][j][3]);
                }
        }
        __syncthreads();

        // ---------- trans block st+1 ----------
        trans_mma(XU, trR + (st + 1) * 8 * 8 * 128, ht, w, lane);
        __syncthreads();
    }

    // ---- dump trans accumulator f32 -> H (reuse P region; X dead) ----
    float* H = s.Pf;
#pragma unroll
    for (int m = 0; m < 2; m++)
#pragma unroll
        for (int j = 0; j < 2; j++) {
            int col = w * 16 + j * 8 + 2 * (lane & 3);
            int row = (lane >> 2) + m * 16;
            *(ull*)&H[row * 128 + col]       = pack2(ht[m][j][0], ht[m][j][1]);
            *(ull*)&H[(row + 8) * 128 + col] = pack2(ht[m][j][2], ht[m][j][3]);
        }
    __syncthreads();

    // ================= LayerNorm + ReLU =================
    {
        const int i0 = w * 4;
        float4 g4 = *(const float4*)(ln_g + c0);
        float4 b4 = *(const float4*)(ln_b + c0);
#pragma unroll
        for (int r = 0; r < 4; r++) {
            int i = i0 + r;
            float4 h = *(const float4*)&H[i * 128 + c0];
            float s1 = h.x + h.y + h.z + h.w;
            float s2 = h.x * h.x + h.y * h.y + h.z * h.z + h.w * h.w;
#pragma unroll
            for (int o = 16; o; o >>= 1) {
                s1 += __shfl_xor_sync(0xffffffffu, s1, o);
                s2 += __shfl_xor_sync(0xffffffffu, s2, o);
            }
            float mu   = s1 * (1.0f / 128.0f);
            float var  = s2 * (1.0f / 128.0f) - mu * mu;
            float rstd = rsqrtf(var + 1e-5f);
            h.x = fmaxf((h.x - mu) * rstd * g4.x + b4.x, 0.0f);
            h.y = fmaxf((h.y - mu) * rstd * g4.y + b4.y, 0.0f);
            h.z = fmaxf((h.z - mu) * rstd * g4.z + b4.z, 0.0f);
            h.w = fmaxf((h.w - mu) * rstd * g4.w + b4.w, 0.0f);
            *(float4*)&H[i * 128 + c0] = h;
        }
    }
    __syncthreads();

    // ================= max-pool + outputs =================
    if (tid < D_) {
        float m = H[tid];
#pragma unroll
        for (int i = 1; i < K_; i++) m = fmaxf(m, H[i * 128 + tid]);
        s.pooled[tid] = m;
        int mm = g >> 6, nn = (g >> 3) & 7, tt = g & 7;
        int p = (tt << 6) + (nn << 3) + mm;          // transpose(0,3,2,1,4)
        out[((long long)b * G_ + p) * D_ + tid] = m;
    }
    __syncthreads();

#pragma unroll
    for (int rr = 0; rr < 4; rr++) {
        int e = tid + TPB * rr;
        int row = e >> 5, c4 = e & 31;
        float4 val = *(const float4*)&s.pooled[c4 * 4];
        *(float4*)(ret + ((long long)b * N_ + s.gidx[row]) * D_ + c4 * 4) = val;
    }
}

extern "C" void kernel_launch(void* const* d_in, const int* in_sizes, int n_in,
                              void* d_out, int out_size)
{
    const float* inputs      = (const float*)d_in[0];
    const float* coordinates = (const float*)d_in[1];
    const float* qkv_w       = (const float*)d_in[2];
    const float* qkv_b       = (const float*)d_in[3];
    const float* table_x     = (const float*)d_in[4];
    const float* table_y     = (const float*)d_in[5];
    const float* table_z     = (const float*)d_in[6];
    const float* trans_w     = (const float*)d_in[7];
    const float* trans_b     = (const float*)d_in[8];
    const float* ln_g        = (const float*)d_in[9];
    const float* ln_b        = (const float*)d_in[10];
    const int*   groups      = (const int*)d_in[11];

    float* out = (float*)d_out;                      // [B, 512, 128]
    float* ret = out + (size_t)B_ * G_ * D_;         // [B, 16384, 128]

    repack_kernel<<<(95232 + TPB - 1) / TPB, TPB>>>(
        qkv_w, trans_w, table_x, table_y, table_z);

    cudaFuncSetAttribute(voxel_encoder_kernel,
                         cudaFuncAttributeMaxDynamicSharedMemorySize,
                         (int)sizeof(Smem));

    voxel_encoder_kernel<<<B_ * G_, TPB, sizeof(Smem)>>>(
        inputs, coordinates, qkv_b, trans_b, ln_g, ln_b, groups, out, ret);
}